// round 10
// baseline (speedup 1.0000x reference)
#include <cuda_runtime.h>
#include <cuda_fp16.h>
#include <stdint.h>

#define TT   8192
#define DDim 2048
#define FFD  8192
#define NE   2
#define PADT 8448      // 66*128
#define STAGE12 98304
#define STAGE3  98304
#define SMEMF  (2*STAGE12)
#define NWD    512

// ---------------- scratch ----------------
__device__ __align__(256) __half g_Xh[(size_t)PADT*DDim];
__device__ __align__(256) __half g_Wg[(size_t)NE*FFD*DDim];
__device__ __align__(256) __half g_Wu[(size_t)NE*FFD*DDim];
__device__ __align__(256) __half g_Wd[(size_t)NE*DDim*FFD];
__device__ __align__(256) __half g_H[(size_t)PADT*FFD];
__device__ int   g_sel[TT];
__device__ float g_topw[TT];
__device__ int   g_tok[PADT];
__device__ int   g_cnt[2];
__device__ int   g_pos[2];
__device__ int   g_qhead;
__device__ int   g_rowdone[66];
__device__ int   g_wddone;

// ---------------- helpers ----------------
__device__ __forceinline__ void cp16(uint32_t saddr, const void* gaddr) {
    asm volatile("cp.async.cg.shared.global [%0], [%1], 16;\n"
                 :: "r"(saddr), "l"(gaddr) : "memory");
}
__device__ __forceinline__ void ldsm4(uint32_t* r, uint32_t addr) {
    asm volatile("ldmatrix.sync.aligned.m8n8.x4.shared.b16 {%0,%1,%2,%3}, [%4];\n"
                 : "=r"(r[0]), "=r"(r[1]), "=r"(r[2]), "=r"(r[3])
                 : "r"(addr) : "memory");
}
__device__ __forceinline__ void mma_f16(float* c, const uint32_t* a, const uint32_t* b) {
    asm volatile("mma.sync.aligned.m16n8k16.row.col.f32.f16.f16.f32 "
                 "{%0,%1,%2,%3}, {%4,%5,%6,%7}, {%8,%9}, {%0,%1,%2,%3};\n"
                 : "+f"(c[0]), "+f"(c[1]), "+f"(c[2]), "+f"(c[3])
                 : "r"(a[0]), "r"(a[1]), "r"(a[2]), "r"(a[3]),
                   "r"(b[0]), "r"(b[1]));
}
__device__ __forceinline__ uint32_t pack_h2(float a, float b) {
    __half2 h = __halves2half2(__float2half(a), __float2half(b));
    return *(uint32_t*)&h;
}

// ---------------- small kernels ----------------
__global__ void init_kernel() {
    int i = blockIdx.x * blockDim.x + threadIdx.x;
    if (i < PADT) g_tok[i] = -1;
    if (i < 66) g_rowdone[i] = 0;
    if (i == 0) {
        g_cnt[0] = 0; g_cnt[1] = 0; g_pos[0] = 0; g_pos[1] = 0;
        g_qhead = 0; g_wddone = 0;
    }
}

__global__ void router_kernel(const float* __restrict__ x, const float* __restrict__ gw) {
    int gt = blockIdx.x * blockDim.x + threadIdx.x;
    int t = gt >> 5, lane = gt & 31;
    if (t >= TT) return;
    const float* xr = x + (size_t)t * DDim;
    float a0 = 0.f, a1 = 0.f;
    for (int d = lane; d < DDim; d += 32) {
        float xv = xr[d];
        a0 += xv * gw[d];
        a1 += xv * gw[DDim + d];
    }
#pragma unroll
    for (int o = 16; o; o >>= 1) {
        a0 += __shfl_xor_sync(0xffffffffu, a0, o);
        a1 += __shfl_xor_sync(0xffffffffu, a1, o);
    }
    if (lane == 0) {
        int sel = (a0 >= a1) ? 0 : 1;
        float m = fmaxf(a0, a1);
        float e0 = expf(a0 - m), e1 = expf(a1 - m);
        float p = ((sel == 0) ? e0 : e1) / (e0 + e1);
        g_sel[t] = sel;
        g_topw[t] = p;
        atomicAdd(&g_cnt[sel], 1);
    }
}

__global__ void assign_kernel() {
    int t = blockIdx.x * blockDim.x + threadIdx.x;
    if (t >= TT) return;
    int sel = g_sel[t];
    int base = sel ? (((g_cnt[0] + 127) >> 7) << 7) : 0;
    int p = atomicAdd(&g_pos[sel], 1);
    g_tok[base + p] = t;
}

__global__ void gatherx_kernel(const float* __restrict__ x) {
    size_t idx = (size_t)blockIdx.x * blockDim.x + threadIdx.x;
    if (idx >= (size_t)PADT * (DDim / 4)) return;
    int r = (int)(idx >> 9);
    int c = (int)(idx & 511);
    int tok = g_tok[r];
    float4 v = make_float4(0.f, 0.f, 0.f, 0.f);
    if (tok >= 0) v = ((const float4*)x)[(size_t)tok * (DDim / 4) + c];
    uint2 o;
    o.x = pack_h2(v.x, v.y);
    o.y = pack_h2(v.z, v.w);
    *(uint2*)(g_Xh + (size_t)r * DDim + (size_t)c * 4) = o;
}

// gate/up weight conversion on stream 2 (event-joined before fused kernel)
__global__ void __launch_bounds__(512)
wconv_gu_kernel(const float* __restrict__ wg, const float* __restrict__ wu) {
    const size_t n8 = (size_t)NE * FFD * DDim / 8;
    size_t idx = (size_t)blockIdx.x * blockDim.x + threadIdx.x;
    if (idx >= n8) return;
    const float* src = (blockIdx.y == 0) ? wg : wu;
    __half* dst = (blockIdx.y == 0) ? g_Wg : g_Wu;
    float4 v0 = ((const float4*)src)[idx * 2];
    float4 v1 = ((const float4*)src)[idx * 2 + 1];
    uint4 o;
    o.x = pack_h2(v0.x, v0.y); o.y = pack_h2(v0.z, v0.w);
    o.z = pack_h2(v1.x, v1.y); o.w = pack_h2(v1.z, v1.w);
    *(uint4*)(dst + idx * 8) = o;
}

// ============ gemm12 body: fused gate+up, tile M128 x N128 x K128-slab ============
struct Frag12 { uint32_t a[4][4]; uint32_t g[4][2]; uint32_t u[4][2]; };

__device__ __forceinline__ void fetch12(Frag12& f, uint32_t sA, uint32_t sBg, uint32_t sBu,
                                        int k16, int wm, int wn,
                                        int lrA, int lcA, int lrB, int lcB) {
    uint32_t hi = (uint32_t)(k16 >> 2) << 14;
    int kk = k16 & 3;
#pragma unroll
    for (int m = 0; m < 4; ++m) {
        int row = wm * 64 + m * 16 + lrA;
        uint32_t off = hi + ((uint32_t)row << 7) + ((uint32_t)((kk * 2 + lcA) ^ (row & 7)) << 4);
        ldsm4(f.a[m], sA + off);
    }
#pragma unroll
    for (int p = 0; p < 2; ++p) {
        int row = wn * 32 + p * 16 + lrB;
        uint32_t off = hi + ((uint32_t)row << 7) + ((uint32_t)((kk * 2 + lcB) ^ (row & 7)) << 4);
        uint32_t r4[4];
        ldsm4(r4, sBg + off);
        f.g[2*p][0] = r4[0]; f.g[2*p][1] = r4[1]; f.g[2*p+1][0] = r4[2]; f.g[2*p+1][1] = r4[3];
        ldsm4(r4, sBu + off);
        f.u[2*p][0] = r4[0]; f.u[2*p][1] = r4[1]; f.u[2*p+1][0] = r4[2]; f.u[2*p+1][1] = r4[3];
    }
}

__device__ __forceinline__ void load_stage12(uint32_t sb, int tid, int k0,
                                             int row0, int bgrow) {
#pragma unroll
    for (int i = 0; i < 24; ++i) {
        int q = tid + (i << 8);
        int mat = q >> 10;
        int q10 = q & 1023;
        int r = q10 >> 3;
        int c = q10 & 7;
        uint32_t so = sb + ((uint32_t)mat << 14) + (r << 7) + ((c ^ (r & 7)) << 4);
        int kk = k0 + ((mat & 1) << 6) + (c << 3);
        int sel = mat >> 1;
        const __half* base = (sel == 0) ? (g_Xh + (size_t)(row0 + r) * DDim)
                           : (sel == 1) ? (g_Wg + (size_t)(bgrow + r) * DDim)
                                        : (g_Wu + (size_t)(bgrow + r) * DDim);
        cp16(so, base + kk);
    }
    asm volatile("cp.async.commit_group;\n" ::: "memory");
}

__device__ void gemm12_body(uint32_t sbase, int tid, int tt, int col, int expert) {
    int row0 = tt << 7;
    int col0 = col << 7;
    int bgrow = expert * FFD + col0;
    int wid = tid >> 5, lane = tid & 31;
    int wm = wid & 1, wn = wid >> 1;
    int lrA = (lane & 7) + (((lane >> 3) & 1) << 3);
    int lcA = lane >> 4;
    int lrB = (lane & 7) + ((lane >> 4) << 3);
    int lcB = (lane >> 3) & 1;

    float ag[4][4][4], au[4][4][4];
#pragma unroll
    for (int m = 0; m < 4; ++m)
#pragma unroll
        for (int n = 0; n < 4; ++n)
#pragma unroll
            for (int i = 0; i < 4; ++i) { ag[m][n][i] = 0.f; au[m][n][i] = 0.f; }

    const int kTiles = DDim >> 7;             // 16
    load_stage12(sbase, tid, 0, row0, bgrow);
    Frag12 fr[2];

    for (int kt = 0; kt < kTiles; ++kt) {
        asm volatile("cp.async.wait_group 0;\n" ::: "memory");
        __syncthreads();
        uint32_t sb = sbase + (uint32_t)(kt & 1) * STAGE12;
        uint32_t sA = sb, sBg = sb + 32768, sBu = sb + 65536;

        fetch12(fr[0], sA, sBg, sBu, 0, wm, wn, lrA, lcA, lrB, lcB);
        if (kt + 1 < kTiles)
            load_stage12(sbase + (uint32_t)((kt + 1) & 1) * STAGE12, tid,
                         (kt + 1) << 7, row0, bgrow);
#pragma unroll
        for (int k16 = 0; k16 < 8; ++k16) {
            int cur = k16 & 1;
            if (k16 < 7)
                fetch12(fr[cur ^ 1], sA, sBg, sBu, k16 + 1, wm, wn, lrA, lcA, lrB, lcB);
#pragma unroll
            for (int m = 0; m < 4; ++m)
#pragma unroll
                for (int n = 0; n < 4; ++n) {
                    mma_f16(ag[m][n], fr[cur].a[m], fr[cur].g[n]);
                    mma_f16(au[m][n], fr[cur].a[m], fr[cur].u[n]);
                }
        }
    }

#pragma unroll
    for (int m = 0; m < 4; ++m) {
        int grow = row0 + wm * 64 + m * 16 + (lane >> 2);
#pragma unroll
        for (int n = 0; n < 4; ++n) {
            int gcol = col0 + wn * 32 + n * 8 + (lane & 3) * 2;
            float h0 = ag[m][n][0] * au[m][n][0] / (1.f + expf(-ag[m][n][0]));
            float h1 = ag[m][n][1] * au[m][n][1] / (1.f + expf(-ag[m][n][1]));
            float h2 = ag[m][n][2] * au[m][n][2] / (1.f + expf(-ag[m][n][2]));
            float h3 = ag[m][n][3] * au[m][n][3] / (1.f + expf(-ag[m][n][3]));
            *(uint32_t*)(g_H + (size_t)grow * FFD + gcol)       = pack_h2(h0, h1);
            *(uint32_t*)(g_H + (size_t)(grow + 8) * FFD + gcol) = pack_h2(h2, h3);
        }
    }
}

// ============ gemm3 body: down proj, tile M128 x N256 x K128-slab ============
struct Frag3 { uint32_t a[4][4]; uint32_t b[8][2]; };

__device__ __forceinline__ void fetch3(Frag3& f, uint32_t sA, uint32_t sB,
                                       int k16, int wm, int wn,
                                       int lrA, int lcA, int lrB, int lcB) {
    uint32_t hiA = (uint32_t)(k16 >> 2) << 14;
    uint32_t hiB = (uint32_t)(k16 >> 2) << 15;
    int kk = k16 & 3;
#pragma unroll
    for (int m = 0; m < 4; ++m) {
        int row = wm * 64 + m * 16 + lrA;
        uint32_t off = hiA + ((uint32_t)row << 7) + ((uint32_t)((kk * 2 + lcA) ^ (row & 7)) << 4);
        ldsm4(f.a[m], sA + off);
    }
#pragma unroll
    for (int p = 0; p < 4; ++p) {
        int row = wn * 64 + p * 16 + lrB;
        uint32_t off = hiB + ((uint32_t)row << 7) + ((uint32_t)((kk * 2 + lcB) ^ (row & 7)) << 4);
        uint32_t r4[4];
        ldsm4(r4, sB + off);
        f.b[2*p][0] = r4[0]; f.b[2*p][1] = r4[1]; f.b[2*p+1][0] = r4[2]; f.b[2*p+1][1] = r4[3];
    }
}

__device__ __forceinline__ void load_stage3(uint32_t sb, int tid, int k0,
                                            int row0, int bdrow) {
#pragma unroll
    for (int i = 0; i < 24; ++i) {
        int q = tid + (i << 8);
        if (q < 2048) {
            int hi = q >> 10;
            int q10 = q & 1023;
            int r = q10 >> 3, c = q10 & 7;
            uint32_t so = sb + ((uint32_t)hi << 14) + (r << 7) + ((c ^ (r & 7)) << 4);
            cp16(so, g_H + (size_t)(row0 + r) * FFD + k0 + (hi << 6) + (c << 3));
        } else {
            int q2 = q - 2048;
            int hi = q2 >> 11;
            int q11 = q2 & 2047;
            int r = q11 >> 3, c = q11 & 7;
            uint32_t so = sb + 32768 + ((uint32_t)hi << 15) + (r << 7) + ((c ^ (r & 7)) << 4);
            cp16(so, g_Wd + (size_t)(bdrow + r) * FFD + k0 + (hi << 6) + (c << 3));
        }
    }
    asm volatile("cp.async.commit_group;\n" ::: "memory");
}

__device__ void gemm3_body(uint32_t sbase, int tid, int tt, int col, int expert,
                           float* __restrict__ outp) {
    int row0 = tt << 7;
    int col0 = col << 8;
    int bdrow = expert * DDim + col0;
    int wid = tid >> 5, lane = tid & 31;
    int wm = wid & 1, wn = wid >> 1;
    int lrA = (lane & 7) + (((lane >> 3) & 1) << 3);
    int lcA = lane >> 4;
    int lrB = (lane & 7) + ((lane >> 4) << 3);
    int lcB = (lane >> 3) & 1;

    float acc[4][8][4];
#pragma unroll
    for (int m = 0; m < 4; ++m)
#pragma unroll
        for (int n = 0; n < 8; ++n)
#pragma unroll
            for (int i = 0; i < 4; ++i) acc[m][n][i] = 0.f;

    const int kTiles = FFD >> 7;              // 64
    load_stage3(sbase, tid, 0, row0, bdrow);
    Frag3 fr[2];

    for (int kt = 0; kt < kTiles; ++kt) {
        asm volatile("cp.async.wait_group 0;\n" ::: "memory");
        __syncthreads();
        uint32_t sb = sbase + (uint32_t)(kt & 1) * STAGE3;
        uint32_t sA = sb, sB = sb + 32768;

        fetch3(fr[0], sA, sB, 0, wm, wn, lrA, lcA, lrB, lcB);
        if (kt + 1 < kTiles)
            load_stage3(sbase + (uint32_t)((kt + 1) & 1) * STAGE3, tid,
                        (kt + 1) << 7, row0, bdrow);
#pragma unroll
        for (int k16 = 0; k16 < 8; ++k16) {
            int cur = k16 & 1;
            if (k16 < 7)
                fetch3(fr[cur ^ 1], sA, sB, k16 + 1, wm, wn, lrA, lcA, lrB, lcB);
#pragma unroll
            for (int m = 0; m < 4; ++m)
#pragma unroll
                for (int n = 0; n < 8; ++n)
                    mma_f16(acc[m][n], fr[cur].a[m], fr[cur].b[n]);
        }
    }

#pragma unroll
    for (int m = 0; m < 4; ++m) {
        int r0g = row0 + wm * 64 + m * 16 + (lane >> 2);
        int tok0 = g_tok[r0g];
        int tok1 = g_tok[r0g + 8];
        float w0 = (tok0 >= 0) ? g_topw[tok0] : 0.f;
        float w1 = (tok1 >= 0) ? g_topw[tok1] : 0.f;
#pragma unroll
        for (int n = 0; n < 8; ++n) {
            int gcol = col0 + wn * 64 + n * 8 + (lane & 3) * 2;
            if (tok0 >= 0) {
                float2 v; v.x = w0 * acc[m][n][0]; v.y = w0 * acc[m][n][1];
                *(float2*)(outp + (size_t)tok0 * DDim + gcol) = v;
            }
            if (tok1 >= 0) {
                float2 v; v.x = w1 * acc[m][n][2]; v.y = w1 * acc[m][n][3];
                *(float2*)(outp + (size_t)tok1 * DDim + gcol) = v;
            }
        }
    }
}

// ============ persistent fused kernel: [gemm12 ROW-major | wd | gemm3] ============
__global__ void __launch_bounds__(256, 1)
fused_gemm_kernel(const float* __restrict__ wd, float* __restrict__ outp)
{
    extern __shared__ char smem[];
    uint32_t sbase = (uint32_t)__cvta_generic_to_shared(smem);
    __shared__ int s_unit;
    int tid = threadIdx.x;

    int n0t = (g_cnt[0] + 127) >> 7, n1t = (g_cnt[1] + 127) >> 7;
    int R = n0t + n1t;
    int NG12 = 64 * R;
    int NTOT = NG12 + NWD + 8 * R;

    for (;;) {
        __syncthreads();
        if (tid == 0) s_unit = atomicAdd(&g_qhead, 1);
        __syncthreads();
        int u = s_unit;
        if (u >= NTOT) return;

        if (u < NG12) {
            // ROW-major: row tt's 64 col-units are consecutive -> rows complete early
            int tt = u >> 6, col = u & 63;
            int expert = (tt < n0t) ? 0 : 1;
            gemm12_body(sbase, tid, tt, col, expert);
            __threadfence();
            __syncthreads();
            if (tid == 0) atomicAdd(&g_rowdone[tt], 1);
        } else if (u < NG12 + NWD) {
            // Wd fp32 -> fp16 conversion unit (overlaps gemm12 tail)
            int w = u - NG12;
            size_t base8 = (size_t)w * 8192;
#pragma unroll 4
            for (int it = 0; it < 32; ++it) {
                size_t idx = base8 + (size_t)it * 256 + tid;
                float4 v0 = ((const float4*)wd)[idx * 2];
                float4 v1 = ((const float4*)wd)[idx * 2 + 1];
                uint4 o;
                o.x = pack_h2(v0.x, v0.y); o.y = pack_h2(v0.z, v0.w);
                o.z = pack_h2(v1.x, v1.y); o.w = pack_h2(v1.z, v1.w);
                *(uint4*)(g_Wd + idx * 8) = o;
            }
            __threadfence();
            __syncthreads();
            if (tid == 0) atomicAdd(&g_wddone, 1);
        } else {
            int v = u - NG12 - NWD;
            int tt = v >> 3, col = v & 7;
            int expert = (tt < n0t) ? 0 : 1;
            if (tid == 0) {
                while (atomicAdd(&g_rowdone[tt], 0) < 64) __nanosleep(128);
                while (atomicAdd(&g_wddone, 0) < NWD)     __nanosleep(128);
            }
            __syncthreads();
            __threadfence();
            gemm3_body(sbase, tid, tt, col, expert, outp);
        }
    }
}

// ---------------- launch ----------------
extern "C" void kernel_launch(void* const* d_in, const int* in_sizes, int n_in,
                              void* d_out, int out_size)
{
    const float* x  = (const float*)d_in[0];
    const float* gw = (const float*)d_in[1];
    const float* wg = (const float*)d_in[2];
    const float* wu = (const float*)d_in[3];
    const float* wd = (const float*)d_in[4];
    float* out = (float*)d_out;

    static cudaStream_t s2 = nullptr;
    static cudaEvent_t evInit = nullptr, evGU = nullptr;
    if (s2 == nullptr) {
        cudaStreamCreateWithFlags(&s2, cudaStreamNonBlocking);
        cudaEventCreateWithFlags(&evInit, cudaEventDisableTiming);
        cudaEventCreateWithFlags(&evGU, cudaEventDisableTiming);
    }

    cudaFuncSetAttribute(fused_gemm_kernel,
                         cudaFuncAttributeMaxDynamicSharedMemorySize, SMEMF);

    init_kernel<<<(PADT + 255) / 256, 256>>>();
    cudaEventRecord(evInit, 0);
    cudaStreamWaitEvent(s2, evInit, 0);

    int wblocks8 = (int)(((size_t)NE * FFD * DDim / 8 + 511) / 512);
    wconv_gu_kernel<<<dim3(wblocks8, 2), 512, 0, s2>>>(wg, wu);
    cudaEventRecord(evGU, s2);

    router_kernel<<<(TT * 32) / 256, 256>>>(x, gw);
    assign_kernel<<<(TT + 255) / 256, 256>>>();
    gatherx_kernel<<<(int)(((size_t)PADT * (DDim / 4) + 255) / 256), 256>>>(x);

    cudaStreamWaitEvent(0, evGU, 0);
    fused_gemm_kernel<<<152, 256, SMEMF>>>(wd, out);
}

// round 11
// speedup vs baseline: 1.2144x; 1.2144x over previous
#include <cuda_runtime.h>
#include <cuda_fp16.h>
#include <stdint.h>

#define TT   8192
#define DDim 2048
#define FFD  8192
#define NE   2
#define PADT 8448      // 66*128
#define NT   66
#define CHUNK 22       // row tiles per pipeline chunk (3 chunks)
#define STAGE12 98304  // [A-lo|A-hi|Bg-lo|Bg-hi|Bu-lo|Bu-hi] 6x16KB
#define STAGE3  98304  // [A-lo|A-hi|B-lo(32K)|B-hi(32K)]
#define SMEM12 (2*STAGE12)
#define SMEM3  (2*STAGE3)

// ---------------- scratch ----------------
__device__ __align__(256) __half g_Xh[(size_t)PADT*DDim];
__device__ __align__(256) __half g_Wg[(size_t)NE*FFD*DDim];
__device__ __align__(256) __half g_Wu[(size_t)NE*FFD*DDim];
__device__ __align__(256) __half g_Wd[(size_t)NE*DDim*FFD];
__device__ __align__(256) __half g_H[(size_t)PADT*FFD];
__device__ int   g_sel[TT];
__device__ float g_topw[TT];
__device__ int   g_tok[PADT];
__device__ int   g_cnt[2];
__device__ int   g_pos[2];

// ---------------- helpers ----------------
__device__ __forceinline__ void cp16(uint32_t saddr, const void* gaddr) {
    asm volatile("cp.async.cg.shared.global [%0], [%1], 16;\n"
                 :: "r"(saddr), "l"(gaddr) : "memory");
}
__device__ __forceinline__ void ldsm4(uint32_t* r, uint32_t addr) {
    asm volatile("ldmatrix.sync.aligned.m8n8.x4.shared.b16 {%0,%1,%2,%3}, [%4];\n"
                 : "=r"(r[0]), "=r"(r[1]), "=r"(r[2]), "=r"(r[3])
                 : "r"(addr) : "memory");
}
__device__ __forceinline__ void mma_f16(float* c, const uint32_t* a, const uint32_t* b) {
    asm volatile("mma.sync.aligned.m16n8k16.row.col.f32.f16.f16.f32 "
                 "{%0,%1,%2,%3}, {%4,%5,%6,%7}, {%8,%9}, {%0,%1,%2,%3};\n"
                 : "+f"(c[0]), "+f"(c[1]), "+f"(c[2]), "+f"(c[3])
                 : "r"(a[0]), "r"(a[1]), "r"(a[2]), "r"(a[3]),
                   "r"(b[0]), "r"(b[1]));
}
__device__ __forceinline__ uint32_t pack_h2(float a, float b) {
    __half2 h = __halves2half2(__float2half(a), __float2half(b));
    return *(uint32_t*)&h;
}

// ---------------- small kernels ----------------
__global__ void init_kernel() {
    int i = blockIdx.x * blockDim.x + threadIdx.x;
    if (i < PADT) g_tok[i] = -1;
    if (i == 0) { g_cnt[0] = 0; g_cnt[1] = 0; g_pos[0] = 0; g_pos[1] = 0; }
}

__global__ void router_kernel(const float* __restrict__ x, const float* __restrict__ gw) {
    int gt = blockIdx.x * blockDim.x + threadIdx.x;
    int t = gt >> 5, lane = gt & 31;
    if (t >= TT) return;
    const float* xr = x + (size_t)t * DDim;
    float a0 = 0.f, a1 = 0.f;
    for (int d = lane; d < DDim; d += 32) {
        float xv = xr[d];
        a0 += xv * gw[d];
        a1 += xv * gw[DDim + d];
    }
#pragma unroll
    for (int o = 16; o; o >>= 1) {
        a0 += __shfl_xor_sync(0xffffffffu, a0, o);
        a1 += __shfl_xor_sync(0xffffffffu, a1, o);
    }
    if (lane == 0) {
        int sel = (a0 >= a1) ? 0 : 1;
        float m = fmaxf(a0, a1);
        float e0 = expf(a0 - m), e1 = expf(a1 - m);
        float p = ((sel == 0) ? e0 : e1) / (e0 + e1);
        g_sel[t] = sel;
        g_topw[t] = p;
        atomicAdd(&g_cnt[sel], 1);
    }
}

__global__ void assign_kernel() {
    int t = blockIdx.x * blockDim.x + threadIdx.x;
    if (t >= TT) return;
    int sel = g_sel[t];
    int base = sel ? (((g_cnt[0] + 127) >> 7) << 7) : 0;
    int p = atomicAdd(&g_pos[sel], 1);
    g_tok[base + p] = t;
}

__global__ void gatherx_kernel(const float* __restrict__ x) {
    size_t idx = (size_t)blockIdx.x * blockDim.x + threadIdx.x;
    if (idx >= (size_t)PADT * (DDim / 4)) return;
    int r = (int)(idx >> 9);
    int c = (int)(idx & 511);
    int tok = g_tok[r];
    float4 v = make_float4(0.f, 0.f, 0.f, 0.f);
    if (tok >= 0) v = ((const float4*)x)[(size_t)tok * (DDim / 4) + c];
    uint2 o;
    o.x = pack_h2(v.x, v.y);
    o.y = pack_h2(v.z, v.w);
    *(uint2*)(g_Xh + (size_t)r * DDim + (size_t)c * 4) = o;
}

__global__ void __launch_bounds__(512)
wconv_gu_kernel(const float* __restrict__ wg, const float* __restrict__ wu) {
    const size_t n8 = (size_t)NE * FFD * DDim / 8;
    size_t idx = (size_t)blockIdx.x * blockDim.x + threadIdx.x;
    if (idx >= n8) return;
    const float* src = (blockIdx.y == 0) ? wg : wu;
    __half* dst = (blockIdx.y == 0) ? g_Wg : g_Wu;
    float4 v0 = ((const float4*)src)[idx * 2];
    float4 v1 = ((const float4*)src)[idx * 2 + 1];
    uint4 o;
    o.x = pack_h2(v0.x, v0.y); o.y = pack_h2(v0.z, v0.w);
    o.z = pack_h2(v1.x, v1.y); o.w = pack_h2(v1.z, v1.w);
    *(uint4*)(dst + idx * 8) = o;
}

__global__ void __launch_bounds__(512)
wconv_d_kernel(const float* __restrict__ wd) {
    const size_t n8 = (size_t)NE * FFD * DDim / 8;
    size_t idx = (size_t)blockIdx.x * blockDim.x + threadIdx.x;
    if (idx >= n8) return;
    float4 v0 = ((const float4*)wd)[idx * 2];
    float4 v1 = ((const float4*)wd)[idx * 2 + 1];
    uint4 o;
    o.x = pack_h2(v0.x, v0.y); o.y = pack_h2(v0.z, v0.w);
    o.z = pack_h2(v1.x, v1.y); o.w = pack_h2(v1.z, v1.w);
    *(uint4*)(g_Wd + idx * 8) = o;
}

// ============ fused gate+up GEMM: tile M128 x N128 x K128-slab ============
struct Frag12 { uint32_t a[4][4]; uint32_t g[4][2]; uint32_t u[4][2]; };

__device__ __forceinline__ void fetch12(Frag12& f, uint32_t sA, uint32_t sBg, uint32_t sBu,
                                        int k16, int wm, int wn,
                                        int lrA, int lcA, int lrB, int lcB) {
    uint32_t hi = (uint32_t)(k16 >> 2) << 14;
    int kk = k16 & 3;
#pragma unroll
    for (int m = 0; m < 4; ++m) {
        int row = wm * 64 + m * 16 + lrA;
        uint32_t off = hi + ((uint32_t)row << 7) + ((uint32_t)((kk * 2 + lcA) ^ (row & 7)) << 4);
        ldsm4(f.a[m], sA + off);
    }
#pragma unroll
    for (int p = 0; p < 2; ++p) {
        int row = wn * 32 + p * 16 + lrB;
        uint32_t off = hi + ((uint32_t)row << 7) + ((uint32_t)((kk * 2 + lcB) ^ (row & 7)) << 4);
        uint32_t r4[4];
        ldsm4(r4, sBg + off);
        f.g[2*p][0] = r4[0]; f.g[2*p][1] = r4[1]; f.g[2*p+1][0] = r4[2]; f.g[2*p+1][1] = r4[3];
        ldsm4(r4, sBu + off);
        f.u[2*p][0] = r4[0]; f.u[2*p][1] = r4[1]; f.u[2*p+1][0] = r4[2]; f.u[2*p+1][1] = r4[3];
    }
}

__device__ __forceinline__ void load_stage12(uint32_t sb, int tid, int k0,
                                             int row0, int bgrow) {
#pragma unroll
    for (int i = 0; i < 24; ++i) {
        int q = tid + (i << 8);
        int mat = q >> 10;
        int q10 = q & 1023;
        int r = q10 >> 3;
        int c = q10 & 7;
        uint32_t so = sb + ((uint32_t)mat << 14) + (r << 7) + ((c ^ (r & 7)) << 4);
        int kk = k0 + ((mat & 1) << 6) + (c << 3);
        int sel = mat >> 1;
        const __half* base = (sel == 0) ? (g_Xh + (size_t)(row0 + r) * DDim)
                           : (sel == 1) ? (g_Wg + (size_t)(bgrow + r) * DDim)
                                        : (g_Wu + (size_t)(bgrow + r) * DDim);
        cp16(so, base + kk);
    }
    asm volatile("cp.async.commit_group;\n" ::: "memory");
}

__global__ void __launch_bounds__(256, 1)
gemm12_kernel(int rowbase)
{
    int n0t = (g_cnt[0] + 127) >> 7, n1t = (g_cnt[1] + 127) >> 7;
    int tt = rowbase + blockIdx.x;
    if (tt >= n0t + n1t) return;
    int expert = (tt < n0t) ? 0 : 1;
    int row0 = tt << 7;
    int col0 = blockIdx.y << 7;
    int bgrow = expert * FFD + col0;

    extern __shared__ char smem[];
    uint32_t sbase = (uint32_t)__cvta_generic_to_shared(smem);
    int tid = threadIdx.x, wid = tid >> 5, lane = tid & 31;
    int wm = wid & 1, wn = wid >> 1;

    int lrA = (lane & 7) + (((lane >> 3) & 1) << 3);
    int lcA = lane >> 4;
    int lrB = (lane & 7) + ((lane >> 4) << 3);
    int lcB = (lane >> 3) & 1;

    float ag[4][4][4], au[4][4][4];
#pragma unroll
    for (int m = 0; m < 4; ++m)
#pragma unroll
        for (int n = 0; n < 4; ++n)
#pragma unroll
            for (int i = 0; i < 4; ++i) { ag[m][n][i] = 0.f; au[m][n][i] = 0.f; }

    const int kTiles = DDim >> 7;             // 16
    load_stage12(sbase, tid, 0, row0, bgrow);
    Frag12 fr[2];

    for (int kt = 0; kt < kTiles; ++kt) {
        asm volatile("cp.async.wait_group 0;\n" ::: "memory");
        __syncthreads();
        uint32_t sb = sbase + (uint32_t)(kt & 1) * STAGE12;
        uint32_t sA = sb, sBg = sb + 32768, sBu = sb + 65536;

        fetch12(fr[0], sA, sBg, sBu, 0, wm, wn, lrA, lcA, lrB, lcB);
        if (kt + 1 < kTiles)
            load_stage12(sbase + (uint32_t)((kt + 1) & 1) * STAGE12, tid,
                         (kt + 1) << 7, row0, bgrow);
#pragma unroll
        for (int k16 = 0; k16 < 8; ++k16) {
            int cur = k16 & 1;
            if (k16 < 7)
                fetch12(fr[cur ^ 1], sA, sBg, sBu, k16 + 1, wm, wn, lrA, lcA, lrB, lcB);
#pragma unroll
            for (int m = 0; m < 4; ++m)
#pragma unroll
                for (int n = 0; n < 4; ++n) {
                    mma_f16(ag[m][n], fr[cur].a[m], fr[cur].g[n]);
                    mma_f16(au[m][n], fr[cur].a[m], fr[cur].u[n]);
                }
        }
    }

    // epilogue: h = silu(g) * u -> fp16 H
#pragma unroll
    for (int m = 0; m < 4; ++m) {
        int grow = row0 + wm * 64 + m * 16 + (lane >> 2);
#pragma unroll
        for (int n = 0; n < 4; ++n) {
            int gcol = col0 + wn * 32 + n * 8 + (lane & 3) * 2;
            float h0 = ag[m][n][0] * au[m][n][0] / (1.f + expf(-ag[m][n][0]));
            float h1 = ag[m][n][1] * au[m][n][1] / (1.f + expf(-ag[m][n][1]));
            float h2 = ag[m][n][2] * au[m][n][2] / (1.f + expf(-ag[m][n][2]));
            float h3 = ag[m][n][3] * au[m][n][3] / (1.f + expf(-ag[m][n][3]));
            *(uint32_t*)(g_H + (size_t)grow * FFD + gcol)       = pack_h2(h0, h1);
            *(uint32_t*)(g_H + (size_t)(grow + 8) * FFD + gcol) = pack_h2(h2, h3);
        }
    }
}

// ============ down GEMM: tile M128 x N256 x K128-slab, weighted scatter ============
struct Frag3 { uint32_t a[4][4]; uint32_t b[8][2]; };

__device__ __forceinline__ void fetch3(Frag3& f, uint32_t sA, uint32_t sB,
                                       int k16, int wm, int wn,
                                       int lrA, int lcA, int lrB, int lcB) {
    uint32_t hiA = (uint32_t)(k16 >> 2) << 14;
    uint32_t hiB = (uint32_t)(k16 >> 2) << 15;
    int kk = k16 & 3;
#pragma unroll
    for (int m = 0; m < 4; ++m) {
        int row = wm * 64 + m * 16 + lrA;
        uint32_t off = hiA + ((uint32_t)row << 7) + ((uint32_t)((kk * 2 + lcA) ^ (row & 7)) << 4);
        ldsm4(f.a[m], sA + off);
    }
#pragma unroll
    for (int p = 0; p < 4; ++p) {
        int row = wn * 64 + p * 16 + lrB;
        uint32_t off = hiB + ((uint32_t)row << 7) + ((uint32_t)((kk * 2 + lcB) ^ (row & 7)) << 4);
        uint32_t r4[4];
        ldsm4(r4, sB + off);
        f.b[2*p][0] = r4[0]; f.b[2*p][1] = r4[1]; f.b[2*p+1][0] = r4[2]; f.b[2*p+1][1] = r4[3];
    }
}

__device__ __forceinline__ void load_stage3(uint32_t sb, int tid, int k0,
                                            int row0, int bdrow) {
#pragma unroll
    for (int i = 0; i < 24; ++i) {
        int q = tid + (i << 8);
        if (q < 2048) {
            int hi = q >> 10;
            int q10 = q & 1023;
            int r = q10 >> 3, c = q10 & 7;
            uint32_t so = sb + ((uint32_t)hi << 14) + (r << 7) + ((c ^ (r & 7)) << 4);
            cp16(so, g_H + (size_t)(row0 + r) * FFD + k0 + (hi << 6) + (c << 3));
        } else {
            int q2 = q - 2048;
            int hi = q2 >> 11;
            int q11 = q2 & 2047;
            int r = q11 >> 3, c = q11 & 7;
            uint32_t so = sb + 32768 + ((uint32_t)hi << 15) + (r << 7) + ((c ^ (r & 7)) << 4);
            cp16(so, g_Wd + (size_t)(bdrow + r) * FFD + k0 + (hi << 6) + (c << 3));
        }
    }
    asm volatile("cp.async.commit_group;\n" ::: "memory");
}

__global__ void __launch_bounds__(256, 1)
gemm3_kernel(int rowbase, float* __restrict__ outp)
{
    int n0t = (g_cnt[0] + 127) >> 7, n1t = (g_cnt[1] + 127) >> 7;
    int tt = rowbase + blockIdx.y;
    if (tt >= n0t + n1t) return;
    int expert = (tt < n0t) ? 0 : 1;
    int row0 = tt << 7;
    int col0 = blockIdx.x << 8;
    int bdrow = expert * DDim + col0;

    extern __shared__ char smem[];
    uint32_t sbase = (uint32_t)__cvta_generic_to_shared(smem);
    int tid = threadIdx.x, wid = tid >> 5, lane = tid & 31;
    int wm = wid & 1, wn = wid >> 1;

    int lrA = (lane & 7) + (((lane >> 3) & 1) << 3);
    int lcA = lane >> 4;
    int lrB = (lane & 7) + ((lane >> 4) << 3);
    int lcB = (lane >> 3) & 1;

    float acc[4][8][4];
#pragma unroll
    for (int m = 0; m < 4; ++m)
#pragma unroll
        for (int n = 0; n < 8; ++n)
#pragma unroll
            for (int i = 0; i < 4; ++i) acc[m][n][i] = 0.f;

    const int kTiles = FFD >> 7;              // 64
    load_stage3(sbase, tid, 0, row0, bdrow);
    Frag3 fr[2];

    for (int kt = 0; kt < kTiles; ++kt) {
        asm volatile("cp.async.wait_group 0;\n" ::: "memory");
        __syncthreads();
        uint32_t sb = sbase + (uint32_t)(kt & 1) * STAGE3;
        uint32_t sA = sb, sB = sb + 32768;

        fetch3(fr[0], sA, sB, 0, wm, wn, lrA, lcA, lrB, lcB);
        if (kt + 1 < kTiles)
            load_stage3(sbase + (uint32_t)((kt + 1) & 1) * STAGE3, tid,
                        (kt + 1) << 7, row0, bdrow);
#pragma unroll
        for (int k16 = 0; k16 < 8; ++k16) {
            int cur = k16 & 1;
            if (k16 < 7)
                fetch3(fr[cur ^ 1], sA, sB, k16 + 1, wm, wn, lrA, lcA, lrB, lcB);
#pragma unroll
            for (int m = 0; m < 4; ++m)
#pragma unroll
                for (int n = 0; n < 8; ++n)
                    mma_f16(acc[m][n], fr[cur].a[m], fr[cur].b[n]);
        }
    }

    // epilogue: scale by routing weight, scatter to token rows
#pragma unroll
    for (int m = 0; m < 4; ++m) {
        int r0g = row0 + wm * 64 + m * 16 + (lane >> 2);
        int tok0 = g_tok[r0g];
        int tok1 = g_tok[r0g + 8];
        float w0 = (tok0 >= 0) ? g_topw[tok0] : 0.f;
        float w1 = (tok1 >= 0) ? g_topw[tok1] : 0.f;
#pragma unroll
        for (int n = 0; n < 8; ++n) {
            int gcol = col0 + wn * 64 + n * 8 + (lane & 3) * 2;
            if (tok0 >= 0) {
                float2 v; v.x = w0 * acc[m][n][0]; v.y = w0 * acc[m][n][1];
                *(float2*)(outp + (size_t)tok0 * DDim + gcol) = v;
            }
            if (tok1 >= 0) {
                float2 v; v.x = w1 * acc[m][n][2]; v.y = w1 * acc[m][n][3];
                *(float2*)(outp + (size_t)tok1 * DDim + gcol) = v;
            }
        }
    }
}

// ---------------- launch ----------------
extern "C" void kernel_launch(void* const* d_in, const int* in_sizes, int n_in,
                              void* d_out, int out_size)
{
    const float* x  = (const float*)d_in[0];
    const float* gw = (const float*)d_in[1];
    const float* wg = (const float*)d_in[2];
    const float* wu = (const float*)d_in[3];
    const float* wd = (const float*)d_in[4];
    float* out = (float*)d_out;

    static cudaStream_t s2 = nullptr, s3 = nullptr;
    static cudaEvent_t evInit = nullptr, evGU = nullptr, evD = nullptr;
    static cudaEvent_t e12a = nullptr, e12b = nullptr, e3s = nullptr;
    if (s2 == nullptr) {
        cudaStreamCreateWithFlags(&s2, cudaStreamNonBlocking);
        cudaStreamCreateWithFlags(&s3, cudaStreamNonBlocking);
        cudaEventCreateWithFlags(&evInit, cudaEventDisableTiming);
        cudaEventCreateWithFlags(&evGU, cudaEventDisableTiming);
        cudaEventCreateWithFlags(&evD, cudaEventDisableTiming);
        cudaEventCreateWithFlags(&e12a, cudaEventDisableTiming);
        cudaEventCreateWithFlags(&e12b, cudaEventDisableTiming);
        cudaEventCreateWithFlags(&e3s, cudaEventDisableTiming);
    }

    cudaFuncSetAttribute(gemm12_kernel, cudaFuncAttributeMaxDynamicSharedMemorySize, SMEM12);
    cudaFuncSetAttribute(gemm3_kernel,  cudaFuncAttributeMaxDynamicSharedMemorySize, SMEM3);

    // init, then fork weight conversion onto s2
    init_kernel<<<(PADT + 255) / 256, 256>>>();
    cudaEventRecord(evInit, 0);
    cudaStreamWaitEvent(s2, evInit, 0);

    int wblocks8 = (int)(((size_t)NE * FFD * DDim / 8 + 511) / 512);
    wconv_gu_kernel<<<dim3(wblocks8, 2), 512, 0, s2>>>(wg, wu);
    cudaEventRecord(evGU, s2);
    wconv_d_kernel<<<wblocks8, 512, 0, s2>>>(wd);
    cudaEventRecord(evD, s2);

    // main: router chain (parallel with wconv on s2)
    router_kernel<<<(TT * 32) / 256, 256>>>(x, gw);
    assign_kernel<<<(TT + 255) / 256, 256>>>();
    gatherx_kernel<<<(int)(((size_t)PADT * (DDim / 4) + 255) / 256), 256>>>(x);

    // gemm12 chunks on main (need gate/up weights)
    cudaStreamWaitEvent(0, evGU, 0);
    gemm12_kernel<<<dim3(CHUNK, FFD / 128), 256, SMEM12>>>(0);
    cudaEventRecord(e12a, 0);
    gemm12_kernel<<<dim3(CHUNK, FFD / 128), 256, SMEM12>>>(CHUNK);
    cudaEventRecord(e12b, 0);
    gemm12_kernel<<<dim3(CHUNK, FFD / 128), 256, SMEM12>>>(2 * CHUNK);

    // gemm3 chunks 0,1 on s3 — backfill gemm12 chunk tails and the boundary
    cudaStreamWaitEvent(s3, evD, 0);
    cudaStreamWaitEvent(s3, e12a, 0);
    gemm3_kernel<<<dim3(DDim / 256, CHUNK), 256, SMEM3, s3>>>(0, out);
    cudaStreamWaitEvent(s3, e12b, 0);
    gemm3_kernel<<<dim3(DDim / 256, CHUNK), 256, SMEM3, s3>>>(CHUNK, out);
    cudaEventRecord(e3s, s3);

    // gemm3 chunk 2 on main (after gemm12 chunk 2 by stream order, Wd by evD)
    cudaStreamWaitEvent(0, evD, 0);
    gemm3_kernel<<<dim3(DDim / 256, CHUNK), 256, SMEM3>>>(2 * CHUNK, out);
    // join s3 so the captured graph's main-stream leaf depends on all work
    cudaStreamWaitEvent(0, e3s, 0);
}

// round 12
// speedup vs baseline: 1.2377x; 1.0192x over previous
#include <cuda_runtime.h>
#include <cuda_fp16.h>
#include <stdint.h>

#define TT   8192
#define DDim 2048
#define FFD  8192
#define NE   2
#define PADT 8448      // 66*128
#define NT   66
#define STAGE12 98304  // [A-lo|A-hi|Bg-lo|Bg-hi|Bu-lo|Bu-hi] 6x16KB
#define STAGE3  65536  // [A-lo|A-hi|B-lo|B-hi] 4x16KB
#define SMEM12 (2*STAGE12)
#define SMEM3  (2*STAGE3)

// ---------------- scratch ----------------
__device__ __align__(256) __half g_Xh[(size_t)PADT*DDim];
__device__ __align__(256) __half g_Wg[(size_t)NE*FFD*DDim];
__device__ __align__(256) __half g_Wu[(size_t)NE*FFD*DDim];
__device__ __align__(256) __half g_Wd[(size_t)NE*DDim*FFD];
__device__ __align__(256) __half g_H[(size_t)PADT*FFD];
__device__ int   g_sel[TT];
__device__ float g_topw[TT];
__device__ int   g_tok[PADT];
__device__ int   g_cnt[2];
__device__ int   g_pos[2];

// ---------------- helpers ----------------
__device__ __forceinline__ void cp16(uint32_t saddr, const void* gaddr) {
    asm volatile("cp.async.cg.shared.global [%0], [%1], 16;\n"
                 :: "r"(saddr), "l"(gaddr) : "memory");
}
__device__ __forceinline__ void ldsm4(uint32_t* r, uint32_t addr) {
    asm volatile("ldmatrix.sync.aligned.m8n8.x4.shared.b16 {%0,%1,%2,%3}, [%4];\n"
                 : "=r"(r[0]), "=r"(r[1]), "=r"(r[2]), "=r"(r[3])
                 : "r"(addr) : "memory");
}
__device__ __forceinline__ void mma_f16(float* c, const uint32_t* a, const uint32_t* b) {
    asm volatile("mma.sync.aligned.m16n8k16.row.col.f32.f16.f16.f32 "
                 "{%0,%1,%2,%3}, {%4,%5,%6,%7}, {%8,%9}, {%0,%1,%2,%3};\n"
                 : "+f"(c[0]), "+f"(c[1]), "+f"(c[2]), "+f"(c[3])
                 : "r"(a[0]), "r"(a[1]), "r"(a[2]), "r"(a[3]),
                   "r"(b[0]), "r"(b[1]));
}
__device__ __forceinline__ uint32_t pack_h2(float a, float b) {
    __half2 h = __halves2half2(__float2half(a), __float2half(b));
    return *(uint32_t*)&h;
}

// ---------------- small kernels ----------------
__global__ void init_kernel() {
    int i = blockIdx.x * blockDim.x + threadIdx.x;
    if (i < PADT) g_tok[i] = -1;
    if (i == 0) { g_cnt[0] = 0; g_cnt[1] = 0; g_pos[0] = 0; g_pos[1] = 0; }
}

__global__ void router_kernel(const float* __restrict__ x, const float* __restrict__ gw) {
    int gt = blockIdx.x * blockDim.x + threadIdx.x;
    int t = gt >> 5, lane = gt & 31;
    if (t >= TT) return;
    const float* xr = x + (size_t)t * DDim;
    float a0 = 0.f, a1 = 0.f;
    for (int d = lane; d < DDim; d += 32) {
        float xv = xr[d];
        a0 += xv * gw[d];
        a1 += xv * gw[DDim + d];
    }
#pragma unroll
    for (int o = 16; o; o >>= 1) {
        a0 += __shfl_xor_sync(0xffffffffu, a0, o);
        a1 += __shfl_xor_sync(0xffffffffu, a1, o);
    }
    if (lane == 0) {
        int sel = (a0 >= a1) ? 0 : 1;
        float m = fmaxf(a0, a1);
        float e0 = expf(a0 - m), e1 = expf(a1 - m);
        float p = ((sel == 0) ? e0 : e1) / (e0 + e1);
        g_sel[t] = sel;
        g_topw[t] = p;
        atomicAdd(&g_cnt[sel], 1);
    }
}

__global__ void assign_kernel() {
    int t = blockIdx.x * blockDim.x + threadIdx.x;
    if (t >= TT) return;
    int sel = g_sel[t];
    int base = sel ? (((g_cnt[0] + 127) >> 7) << 7) : 0;
    int p = atomicAdd(&g_pos[sel], 1);
    g_tok[base + p] = t;
}

__global__ void gatherx_kernel(const float* __restrict__ x) {
    size_t idx = (size_t)blockIdx.x * blockDim.x + threadIdx.x;
    if (idx >= (size_t)PADT * (DDim / 4)) return;
    int r = (int)(idx >> 9);
    int c = (int)(idx & 511);
    int tok = g_tok[r];
    float4 v = make_float4(0.f, 0.f, 0.f, 0.f);
    if (tok >= 0) v = ((const float4*)x)[(size_t)tok * (DDim / 4) + c];
    uint2 o;
    o.x = pack_h2(v.x, v.y);
    o.y = pack_h2(v.z, v.w);
    *(uint2*)(g_Xh + (size_t)r * DDim + (size_t)c * 4) = o;
}

__global__ void __launch_bounds__(512)
wconv_gu_kernel(const float* __restrict__ wg, const float* __restrict__ wu) {
    const size_t n8 = (size_t)NE * FFD * DDim / 8;
    size_t idx = (size_t)blockIdx.x * blockDim.x + threadIdx.x;
    if (idx >= n8) return;
    const float* src = (blockIdx.y == 0) ? wg : wu;
    __half* dst = (blockIdx.y == 0) ? g_Wg : g_Wu;
    float4 v0 = ((const float4*)src)[idx * 2];
    float4 v1 = ((const float4*)src)[idx * 2 + 1];
    uint4 o;
    o.x = pack_h2(v0.x, v0.y); o.y = pack_h2(v0.z, v0.w);
    o.z = pack_h2(v1.x, v1.y); o.w = pack_h2(v1.z, v1.w);
    *(uint4*)(dst + idx * 8) = o;
}

__global__ void __launch_bounds__(512)
wconv_d_kernel(const float* __restrict__ wd) {
    const size_t n8 = (size_t)NE * FFD * DDim / 8;
    size_t idx = (size_t)blockIdx.x * blockDim.x + threadIdx.x;
    if (idx >= n8) return;
    float4 v0 = ((const float4*)wd)[idx * 2];
    float4 v1 = ((const float4*)wd)[idx * 2 + 1];
    uint4 o;
    o.x = pack_h2(v0.x, v0.y); o.y = pack_h2(v0.z, v0.w);
    o.z = pack_h2(v1.x, v1.y); o.w = pack_h2(v1.z, v1.w);
    *(uint4*)(g_Wd + idx * 8) = o;
}

// ============ fused gate+up GEMM: tile M128 x N128 x K128-slab ============
struct Frag12 { uint32_t a[4][4]; uint32_t g[4][2]; uint32_t u[4][2]; };

__device__ __forceinline__ void fetch12(Frag12& f, uint32_t sA, uint32_t sBg, uint32_t sBu,
                                        int k16, int wm, int wn,
                                        int lrA, int lcA, int lrB, int lcB) {
    uint32_t hi = (uint32_t)(k16 >> 2) << 14;
    int kk = k16 & 3;
#pragma unroll
    for (int m = 0; m < 4; ++m) {
        int row = wm * 64 + m * 16 + lrA;
        uint32_t off = hi + ((uint32_t)row << 7) + ((uint32_t)((kk * 2 + lcA) ^ (row & 7)) << 4);
        ldsm4(f.a[m], sA + off);
    }
#pragma unroll
    for (int p = 0; p < 2; ++p) {
        int row = wn * 32 + p * 16 + lrB;
        uint32_t off = hi + ((uint32_t)row << 7) + ((uint32_t)((kk * 2 + lcB) ^ (row & 7)) << 4);
        uint32_t r4[4];
        ldsm4(r4, sBg + off);
        f.g[2*p][0] = r4[0]; f.g[2*p][1] = r4[1]; f.g[2*p+1][0] = r4[2]; f.g[2*p+1][1] = r4[3];
        ldsm4(r4, sBu + off);
        f.u[2*p][0] = r4[0]; f.u[2*p][1] = r4[1]; f.u[2*p+1][0] = r4[2]; f.u[2*p+1][1] = r4[3];
    }
}

__device__ __forceinline__ void load_stage12(uint32_t sb, int tid, int k0,
                                             int row0, int bgrow) {
#pragma unroll
    for (int i = 0; i < 24; ++i) {
        int q = tid + (i << 8);
        int mat = q >> 10;
        int q10 = q & 1023;
        int r = q10 >> 3;
        int c = q10 & 7;
        uint32_t so = sb + ((uint32_t)mat << 14) + (r << 7) + ((c ^ (r & 7)) << 4);
        int kk = k0 + ((mat & 1) << 6) + (c << 3);
        int sel = mat >> 1;
        const __half* base = (sel == 0) ? (g_Xh + (size_t)(row0 + r) * DDim)
                           : (sel == 1) ? (g_Wg + (size_t)(bgrow + r) * DDim)
                                        : (g_Wu + (size_t)(bgrow + r) * DDim);
        cp16(so, base + kk);
    }
    asm volatile("cp.async.commit_group;\n" ::: "memory");
}

__global__ void __launch_bounds__(256, 1)
gemm12_kernel()
{
    int n0t = (g_cnt[0] + 127) >> 7, n1t = (g_cnt[1] + 127) >> 7;
    int tt = blockIdx.x;
    if (tt >= n0t + n1t) return;
    int expert = (tt < n0t) ? 0 : 1;
    int row0 = tt << 7;
    int col0 = blockIdx.y << 7;
    int bgrow = expert * FFD + col0;

    extern __shared__ char smem[];
    uint32_t sbase = (uint32_t)__cvta_generic_to_shared(smem);
    int tid = threadIdx.x, wid = tid >> 5, lane = tid & 31;
    int wm = wid & 1, wn = wid >> 1;

    int lrA = (lane & 7) + (((lane >> 3) & 1) << 3);
    int lcA = lane >> 4;
    int lrB = (lane & 7) + ((lane >> 4) << 3);
    int lcB = (lane >> 3) & 1;

    float ag[4][4][4], au[4][4][4];
#pragma unroll
    for (int m = 0; m < 4; ++m)
#pragma unroll
        for (int n = 0; n < 4; ++n)
#pragma unroll
            for (int i = 0; i < 4; ++i) { ag[m][n][i] = 0.f; au[m][n][i] = 0.f; }

    const int kTiles = DDim >> 7;             // 16
    load_stage12(sbase, tid, 0, row0, bgrow);
    Frag12 fr[2];

    for (int kt = 0; kt < kTiles; ++kt) {
        asm volatile("cp.async.wait_group 0;\n" ::: "memory");
        __syncthreads();
        uint32_t sb = sbase + (uint32_t)(kt & 1) * STAGE12;
        uint32_t sA = sb, sBg = sb + 32768, sBu = sb + 65536;

        fetch12(fr[0], sA, sBg, sBu, 0, wm, wn, lrA, lcA, lrB, lcB);
        if (kt + 1 < kTiles)
            load_stage12(sbase + (uint32_t)((kt + 1) & 1) * STAGE12, tid,
                         (kt + 1) << 7, row0, bgrow);
#pragma unroll
        for (int k16 = 0; k16 < 8; ++k16) {
            int cur = k16 & 1;
            if (k16 < 7)
                fetch12(fr[cur ^ 1], sA, sBg, sBu, k16 + 1, wm, wn, lrA, lcA, lrB, lcB);
#pragma unroll
            for (int m = 0; m < 4; ++m)
#pragma unroll
                for (int n = 0; n < 4; ++n) {
                    mma_f16(ag[m][n], fr[cur].a[m], fr[cur].g[n]);
                    mma_f16(au[m][n], fr[cur].a[m], fr[cur].u[n]);
                }
        }
    }

    // epilogue: h = silu(g) * u -> fp16 H
#pragma unroll
    for (int m = 0; m < 4; ++m) {
        int grow = row0 + wm * 64 + m * 16 + (lane >> 2);
#pragma unroll
        for (int n = 0; n < 4; ++n) {
            int gcol = col0 + wn * 32 + n * 8 + (lane & 3) * 2;
            float h0 = ag[m][n][0] * au[m][n][0] / (1.f + expf(-ag[m][n][0]));
            float h1 = ag[m][n][1] * au[m][n][1] / (1.f + expf(-ag[m][n][1]));
            float h2 = ag[m][n][2] * au[m][n][2] / (1.f + expf(-ag[m][n][2]));
            float h3 = ag[m][n][3] * au[m][n][3] / (1.f + expf(-ag[m][n][3]));
            *(uint32_t*)(g_H + (size_t)grow * FFD + gcol)       = pack_h2(h0, h1);
            *(uint32_t*)(g_H + (size_t)(grow + 8) * FFD + gcol) = pack_h2(h2, h3);
        }
    }
}

// ============ down GEMM: tile M128 x N128 x K128-slab (fine grid for wave fill) ============
struct Frag3 { uint32_t a[4][4]; uint32_t b[4][2]; };

__device__ __forceinline__ void fetch3(Frag3& f, uint32_t sA, uint32_t sB,
                                       int k16, int wm, int wn,
                                       int lrA, int lcA, int lrB, int lcB) {
    uint32_t hi = (uint32_t)(k16 >> 2) << 14;
    int kk = k16 & 3;
#pragma unroll
    for (int m = 0; m < 4; ++m) {
        int row = wm * 64 + m * 16 + lrA;
        uint32_t off = hi + ((uint32_t)row << 7) + ((uint32_t)((kk * 2 + lcA) ^ (row & 7)) << 4);
        ldsm4(f.a[m], sA + off);
    }
#pragma unroll
    for (int p = 0; p < 2; ++p) {
        int row = wn * 32 + p * 16 + lrB;
        uint32_t off = hi + ((uint32_t)row << 7) + ((uint32_t)((kk * 2 + lcB) ^ (row & 7)) << 4);
        uint32_t r4[4];
        ldsm4(r4, sB + off);
        f.b[2*p][0] = r4[0]; f.b[2*p][1] = r4[1]; f.b[2*p+1][0] = r4[2]; f.b[2*p+1][1] = r4[3];
    }
}

// stage layout: [A-lo 16K | A-hi 16K | B-lo 16K | B-hi 16K]
__device__ __forceinline__ void load_stage3(uint32_t sb, int tid, int k0,
                                            int row0, int bdrow) {
#pragma unroll
    for (int i = 0; i < 16; ++i) {
        int q = tid + (i << 8);               // 4096 chunks
        int half = q >> 11;                   // 0:A 1:B
        int q2 = q & 2047;
        int hi = q2 >> 10;                    // k-lo / k-hi sub-tile
        int q10 = q2 & 1023;
        int r = q10 >> 3, c = q10 & 7;
        uint32_t so = sb + ((uint32_t)half << 15) + ((uint32_t)hi << 14)
                    + (r << 7) + ((c ^ (r & 7)) << 4);
        const __half* base = half ? (g_Wd + (size_t)(bdrow + r) * FFD)
                                  : (g_H  + (size_t)(row0 + r) * FFD);
        cp16(so, base + k0 + (hi << 6) + (c << 3));
    }
    asm volatile("cp.async.commit_group;\n" ::: "memory");
}

__global__ void __launch_bounds__(256, 1)
gemm3_kernel(float* __restrict__ outp)
{
    int n0t = (g_cnt[0] + 127) >> 7, n1t = (g_cnt[1] + 127) >> 7;
    int tt = blockIdx.y;
    if (tt >= n0t + n1t) return;
    int expert = (tt < n0t) ? 0 : 1;
    int row0 = tt << 7;
    int col0 = blockIdx.x << 7;               // 128-wide col tiles
    int bdrow = expert * DDim + col0;

    extern __shared__ char smem[];
    uint32_t sbase = (uint32_t)__cvta_generic_to_shared(smem);
    int tid = threadIdx.x, wid = tid >> 5, lane = tid & 31;
    int wm = wid & 1, wn = wid >> 1;

    int lrA = (lane & 7) + (((lane >> 3) & 1) << 3);
    int lcA = lane >> 4;
    int lrB = (lane & 7) + ((lane >> 4) << 3);
    int lcB = (lane >> 3) & 1;

    float acc[4][4][4];
#pragma unroll
    for (int m = 0; m < 4; ++m)
#pragma unroll
        for (int n = 0; n < 4; ++n)
#pragma unroll
            for (int i = 0; i < 4; ++i) acc[m][n][i] = 0.f;

    const int kTiles = FFD >> 7;              // 64
    load_stage3(sbase, tid, 0, row0, bdrow);
    Frag3 fr[2];

    for (int kt = 0; kt < kTiles; ++kt) {
        asm volatile("cp.async.wait_group 0;\n" ::: "memory");
        __syncthreads();
        uint32_t sb = sbase + (uint32_t)(kt & 1) * STAGE3;
        uint32_t sA = sb, sB = sb + 32768;

        fetch3(fr[0], sA, sB, 0, wm, wn, lrA, lcA, lrB, lcB);
        if (kt + 1 < kTiles)
            load_stage3(sbase + (uint32_t)((kt + 1) & 1) * STAGE3, tid,
                        (kt + 1) << 7, row0, bdrow);
#pragma unroll
        for (int k16 = 0; k16 < 8; ++k16) {
            int cur = k16 & 1;
            if (k16 < 7)
                fetch3(fr[cur ^ 1], sA, sB, k16 + 1, wm, wn, lrA, lcA, lrB, lcB);
#pragma unroll
            for (int m = 0; m < 4; ++m)
#pragma unroll
                for (int n = 0; n < 4; ++n)
                    mma_f16(acc[m][n], fr[cur].a[m], fr[cur].b[n]);
        }
    }

    // epilogue: scale by routing weight, scatter to token rows
#pragma unroll
    for (int m = 0; m < 4; ++m) {
        int r0g = row0 + wm * 64 + m * 16 + (lane >> 2);
        int tok0 = g_tok[r0g];
        int tok1 = g_tok[r0g + 8];
        float w0 = (tok0 >= 0) ? g_topw[tok0] : 0.f;
        float w1 = (tok1 >= 0) ? g_topw[tok1] : 0.f;
#pragma unroll
        for (int n = 0; n < 4; ++n) {
            int gcol = col0 + wn * 32 + n * 8 + (lane & 3) * 2;
            if (tok0 >= 0) {
                float2 v; v.x = w0 * acc[m][n][0]; v.y = w0 * acc[m][n][1];
                *(float2*)(outp + (size_t)tok0 * DDim + gcol) = v;
            }
            if (tok1 >= 0) {
                float2 v; v.x = w1 * acc[m][n][2]; v.y = w1 * acc[m][n][3];
                *(float2*)(outp + (size_t)tok1 * DDim + gcol) = v;
            }
        }
    }
}

// ---------------- launch ----------------
extern "C" void kernel_launch(void* const* d_in, const int* in_sizes, int n_in,
                              void* d_out, int out_size)
{
    const float* x  = (const float*)d_in[0];
    const float* gw = (const float*)d_in[1];
    const float* wg = (const float*)d_in[2];
    const float* wu = (const float*)d_in[3];
    const float* wd = (const float*)d_in[4];
    float* out = (float*)d_out;

    static cudaStream_t s2 = nullptr;
    static cudaEvent_t evFork = nullptr, evGU = nullptr, evD = nullptr;
    if (s2 == nullptr) {
        cudaStreamCreateWithFlags(&s2, cudaStreamNonBlocking);
        cudaEventCreateWithFlags(&evFork, cudaEventDisableTiming);
        cudaEventCreateWithFlags(&evGU, cudaEventDisableTiming);
        cudaEventCreateWithFlags(&evD, cudaEventDisableTiming);
    }

    cudaFuncSetAttribute(gemm12_kernel, cudaFuncAttributeMaxDynamicSharedMemorySize, SMEM12);
    cudaFuncSetAttribute(gemm3_kernel,  cudaFuncAttributeMaxDynamicSharedMemorySize, SMEM3);

    // fork wconv at the VERY start (it shares no state with init/router chain)
    cudaEventRecord(evFork, 0);
    cudaStreamWaitEvent(s2, evFork, 0);

    int wblocks8 = (int)(((size_t)NE * FFD * DDim / 8 + 511) / 512);
    wconv_gu_kernel<<<dim3(wblocks8, 2), 512, 0, s2>>>(wg, wu);
    cudaEventRecord(evGU, s2);
    wconv_d_kernel<<<wblocks8, 512, 0, s2>>>(wd);
    cudaEventRecord(evD, s2);

    // main: router chain (parallel with wconv)
    init_kernel<<<(PADT + 255) / 256, 256>>>();
    router_kernel<<<(TT * 32) / 256, 256>>>(x, gw);
    assign_kernel<<<(TT + 255) / 256, 256>>>();
    gatherx_kernel<<<(int)(((size_t)PADT * (DDim / 4) + 255) / 256), 256>>>(x);

    cudaStreamWaitEvent(0, evGU, 0);
    gemm12_kernel<<<dim3(NT, FFD / 128), 256, SMEM12>>>();

    cudaStreamWaitEvent(0, evD, 0);
    gemm3_kernel<<<dim3(DDim / 128, NT), 256, SMEM3>>>(out);
}

// round 13
// speedup vs baseline: 1.2403x; 1.0021x over previous
#include <cuda_runtime.h>
#include <cuda_fp16.h>
#include <stdint.h>

#define TT   8192
#define DDim 2048
#define FFD  8192
#define NE   2
#define PADT 8448      // 66*128
#define NT   66
#define STAGE12 98304  // [A-lo|A-hi|Bg-lo|Bg-hi|Bu-lo|Bu-hi] 6x16KB
#define STAGE3  65536  // [A-lo|A-hi|B-lo|B-hi] 4x16KB
#define SMEM12 (2*STAGE12)
#define SMEM3  (2*STAGE3)

// ---------------- scratch ----------------
__device__ __align__(256) __half g_Xh[(size_t)PADT*DDim];
__device__ __align__(256) __half g_Wg[(size_t)NE*FFD*DDim];
__device__ __align__(256) __half g_Wu[(size_t)NE*FFD*DDim];
__device__ __align__(256) __half g_Wd[(size_t)NE*DDim*FFD];
__device__ __align__(256) __half g_H[(size_t)PADT*FFD];
__device__ int   g_sel[TT];
__device__ float g_topw[TT];
__device__ int   g_tok[PADT];
__device__ int   g_cnt[2];
__device__ int   g_pos[2];

// ---------------- helpers ----------------
__device__ __forceinline__ void cp16(uint32_t saddr, const void* gaddr) {
    asm volatile("cp.async.cg.shared.global [%0], [%1], 16;\n"
                 :: "r"(saddr), "l"(gaddr) : "memory");
}
__device__ __forceinline__ void ldsm4(uint32_t* r, uint32_t addr) {
    asm volatile("ldmatrix.sync.aligned.m8n8.x4.shared.b16 {%0,%1,%2,%3}, [%4];\n"
                 : "=r"(r[0]), "=r"(r[1]), "=r"(r[2]), "=r"(r[3])
                 : "r"(addr) : "memory");
}
__device__ __forceinline__ void mma_f16(float* c, const uint32_t* a, const uint32_t* b) {
    asm volatile("mma.sync.aligned.m16n8k16.row.col.f32.f16.f16.f32 "
                 "{%0,%1,%2,%3}, {%4,%5,%6,%7}, {%8,%9}, {%0,%1,%2,%3};\n"
                 : "+f"(c[0]), "+f"(c[1]), "+f"(c[2]), "+f"(c[3])
                 : "r"(a[0]), "r"(a[1]), "r"(a[2]), "r"(a[3]),
                   "r"(b[0]), "r"(b[1]));
}
__device__ __forceinline__ uint32_t pack_h2(float a, float b) {
    __half2 h = __halves2half2(__float2half(a), __float2half(b));
    return *(uint32_t*)&h;
}

// ---------------- small kernels ----------------
__global__ void init_kernel() {
    int i = blockIdx.x * blockDim.x + threadIdx.x;
    if (i < PADT) g_tok[i] = -1;
    if (i == 0) { g_cnt[0] = 0; g_cnt[1] = 0; g_pos[0] = 0; g_pos[1] = 0; }
}

__global__ void router_kernel(const float* __restrict__ x, const float* __restrict__ gw) {
    int gt = blockIdx.x * blockDim.x + threadIdx.x;
    int t = gt >> 5, lane = gt & 31;
    if (t >= TT) return;
    const float* xr = x + (size_t)t * DDim;
    float a0 = 0.f, a1 = 0.f;
#pragma unroll 4
    for (int d = lane * 4; d < DDim; d += 128) {
        float4 xv = *(const float4*)(xr + d);
        float4 w0 = *(const float4*)(gw + d);
        float4 w1 = *(const float4*)(gw + DDim + d);
        a0 += xv.x * w0.x + xv.y * w0.y + xv.z * w0.z + xv.w * w0.w;
        a1 += xv.x * w1.x + xv.y * w1.y + xv.z * w1.z + xv.w * w1.w;
    }
#pragma unroll
    for (int o = 16; o; o >>= 1) {
        a0 += __shfl_xor_sync(0xffffffffu, a0, o);
        a1 += __shfl_xor_sync(0xffffffffu, a1, o);
    }
    if (lane == 0) {
        int sel = (a0 >= a1) ? 0 : 1;
        float m = fmaxf(a0, a1);
        float e0 = expf(a0 - m), e1 = expf(a1 - m);
        float p = ((sel == 0) ? e0 : e1) / (e0 + e1);
        g_sel[t] = sel;
        g_topw[t] = p;
        atomicAdd(&g_cnt[sel], 1);
    }
}

// fused assign + gather: one warp per token claims a slot, copies/converts the row.
// pad rows keep stale data — harmless: their outputs are discarded via tok<0 guard.
__global__ void assign_gather_kernel(const float* __restrict__ x) {
    int gt = blockIdx.x * blockDim.x + threadIdx.x;
    int t = gt >> 5, lane = gt & 31;
    if (t >= TT) return;
    int slot = 0;
    if (lane == 0) {
        int sel = g_sel[t];
        int base = sel ? (((g_cnt[0] + 127) >> 7) << 7) : 0;
        int p = atomicAdd(&g_pos[sel], 1);
        slot = base + p;
        g_tok[slot] = t;
    }
    slot = __shfl_sync(0xffffffffu, slot, 0);
    const float4* xr = (const float4*)(x + (size_t)t * DDim);
    __half* dst = g_Xh + (size_t)slot * DDim;
#pragma unroll 4
    for (int c = lane; c < DDim / 4; c += 32) {
        float4 v = xr[c];
        uint2 o;
        o.x = pack_h2(v.x, v.y);
        o.y = pack_h2(v.z, v.w);
        *(uint2*)(dst + c * 4) = o;
    }
}

__global__ void __launch_bounds__(512)
wconv_gu_kernel(const float* __restrict__ wg, const float* __restrict__ wu) {
    const size_t n8 = (size_t)NE * FFD * DDim / 8;
    size_t idx = (size_t)blockIdx.x * blockDim.x + threadIdx.x;
    if (idx >= n8) return;
    const float* src = (blockIdx.y == 0) ? wg : wu;
    __half* dst = (blockIdx.y == 0) ? g_Wg : g_Wu;
    float4 v0 = ((const float4*)src)[idx * 2];
    float4 v1 = ((const float4*)src)[idx * 2 + 1];
    uint4 o;
    o.x = pack_h2(v0.x, v0.y); o.y = pack_h2(v0.z, v0.w);
    o.z = pack_h2(v1.x, v1.y); o.w = pack_h2(v1.z, v1.w);
    *(uint4*)(dst + idx * 8) = o;
}

__global__ void __launch_bounds__(512)
wconv_d_kernel(const float* __restrict__ wd) {
    const size_t n8 = (size_t)NE * FFD * DDim / 8;
    size_t idx = (size_t)blockIdx.x * blockDim.x + threadIdx.x;
    if (idx >= n8) return;
    float4 v0 = ((const float4*)wd)[idx * 2];
    float4 v1 = ((const float4*)wd)[idx * 2 + 1];
    uint4 o;
    o.x = pack_h2(v0.x, v0.y); o.y = pack_h2(v0.z, v0.w);
    o.z = pack_h2(v1.x, v1.y); o.w = pack_h2(v1.z, v1.w);
    *(uint4*)(g_Wd + idx * 8) = o;
}

// ============ fused gate+up GEMM: tile M128 x N128 x K128-slab ============
struct Frag12 { uint32_t a[4][4]; uint32_t g[4][2]; uint32_t u[4][2]; };

__device__ __forceinline__ void fetch12(Frag12& f, uint32_t sA, uint32_t sBg, uint32_t sBu,
                                        int k16, int wm, int wn,
                                        int lrA, int lcA, int lrB, int lcB) {
    uint32_t hi = (uint32_t)(k16 >> 2) << 14;
    int kk = k16 & 3;
#pragma unroll
    for (int m = 0; m < 4; ++m) {
        int row = wm * 64 + m * 16 + lrA;
        uint32_t off = hi + ((uint32_t)row << 7) + ((uint32_t)((kk * 2 + lcA) ^ (row & 7)) << 4);
        ldsm4(f.a[m], sA + off);
    }
#pragma unroll
    for (int p = 0; p < 2; ++p) {
        int row = wn * 32 + p * 16 + lrB;
        uint32_t off = hi + ((uint32_t)row << 7) + ((uint32_t)((kk * 2 + lcB) ^ (row & 7)) << 4);
        uint32_t r4[4];
        ldsm4(r4, sBg + off);
        f.g[2*p][0] = r4[0]; f.g[2*p][1] = r4[1]; f.g[2*p+1][0] = r4[2]; f.g[2*p+1][1] = r4[3];
        ldsm4(r4, sBu + off);
        f.u[2*p][0] = r4[0]; f.u[2*p][1] = r4[1]; f.u[2*p+1][0] = r4[2]; f.u[2*p+1][1] = r4[3];
    }
}

__device__ __forceinline__ void load_stage12(uint32_t sb, int tid, int k0,
                                             int row0, int bgrow) {
#pragma unroll
    for (int i = 0; i < 24; ++i) {
        int q = tid + (i << 8);
        int mat = q >> 10;
        int q10 = q & 1023;
        int r = q10 >> 3;
        int c = q10 & 7;
        uint32_t so = sb + ((uint32_t)mat << 14) + (r << 7) + ((c ^ (r & 7)) << 4);
        int kk = k0 + ((mat & 1) << 6) + (c << 3);
        int sel = mat >> 1;
        const __half* base = (sel == 0) ? (g_Xh + (size_t)(row0 + r) * DDim)
                           : (sel == 1) ? (g_Wg + (size_t)(bgrow + r) * DDim)
                                        : (g_Wu + (size_t)(bgrow + r) * DDim);
        cp16(so, base + kk);
    }
    asm volatile("cp.async.commit_group;\n" ::: "memory");
}

__global__ void __launch_bounds__(256, 1)
gemm12_kernel()
{
    int n0t = (g_cnt[0] + 127) >> 7, n1t = (g_cnt[1] + 127) >> 7;
    int tt = blockIdx.x;
    if (tt >= n0t + n1t) return;
    int expert = (tt < n0t) ? 0 : 1;
    int row0 = tt << 7;
    int col0 = blockIdx.y << 7;
    int bgrow = expert * FFD + col0;

    extern __shared__ char smem[];
    uint32_t sbase = (uint32_t)__cvta_generic_to_shared(smem);
    int tid = threadIdx.x, wid = tid >> 5, lane = tid & 31;
    int wm = wid & 1, wn = wid >> 1;

    int lrA = (lane & 7) + (((lane >> 3) & 1) << 3);
    int lcA = lane >> 4;
    int lrB = (lane & 7) + ((lane >> 4) << 3);
    int lcB = (lane >> 3) & 1;

    float ag[4][4][4], au[4][4][4];
#pragma unroll
    for (int m = 0; m < 4; ++m)
#pragma unroll
        for (int n = 0; n < 4; ++n)
#pragma unroll
            for (int i = 0; i < 4; ++i) { ag[m][n][i] = 0.f; au[m][n][i] = 0.f; }

    const int kTiles = DDim >> 7;             // 16
    load_stage12(sbase, tid, 0, row0, bgrow);
    Frag12 fr[2];

    for (int kt = 0; kt < kTiles; ++kt) {
        asm volatile("cp.async.wait_group 0;\n" ::: "memory");
        __syncthreads();
        uint32_t sb = sbase + (uint32_t)(kt & 1) * STAGE12;
        uint32_t sA = sb, sBg = sb + 32768, sBu = sb + 65536;

        fetch12(fr[0], sA, sBg, sBu, 0, wm, wn, lrA, lcA, lrB, lcB);
        if (kt + 1 < kTiles)
            load_stage12(sbase + (uint32_t)((kt + 1) & 1) * STAGE12, tid,
                         (kt + 1) << 7, row0, bgrow);
#pragma unroll
        for (int k16 = 0; k16 < 8; ++k16) {
            int cur = k16 & 1;
            if (k16 < 7)
                fetch12(fr[cur ^ 1], sA, sBg, sBu, k16 + 1, wm, wn, lrA, lcA, lrB, lcB);
#pragma unroll
            for (int m = 0; m < 4; ++m)
#pragma unroll
                for (int n = 0; n < 4; ++n) {
                    mma_f16(ag[m][n], fr[cur].a[m], fr[cur].g[n]);
                    mma_f16(au[m][n], fr[cur].a[m], fr[cur].u[n]);
                }
        }
    }

    // epilogue: h = silu(g) * u -> fp16 H
#pragma unroll
    for (int m = 0; m < 4; ++m) {
        int grow = row0 + wm * 64 + m * 16 + (lane >> 2);
#pragma unroll
        for (int n = 0; n < 4; ++n) {
            int gcol = col0 + wn * 32 + n * 8 + (lane & 3) * 2;
            float h0 = ag[m][n][0] * au[m][n][0] / (1.f + expf(-ag[m][n][0]));
            float h1 = ag[m][n][1] * au[m][n][1] / (1.f + expf(-ag[m][n][1]));
            float h2 = ag[m][n][2] * au[m][n][2] / (1.f + expf(-ag[m][n][2]));
            float h3 = ag[m][n][3] * au[m][n][3] / (1.f + expf(-ag[m][n][3]));
            *(uint32_t*)(g_H + (size_t)grow * FFD + gcol)       = pack_h2(h0, h1);
            *(uint32_t*)(g_H + (size_t)(grow + 8) * FFD + gcol) = pack_h2(h2, h3);
        }
    }
}

// ============ down GEMM: tile M128 x N128 x K128-slab (fine grid for wave fill) ============
struct Frag3 { uint32_t a[4][4]; uint32_t b[4][2]; };

__device__ __forceinline__ void fetch3(Frag3& f, uint32_t sA, uint32_t sB,
                                       int k16, int wm, int wn,
                                       int lrA, int lcA, int lrB, int lcB) {
    uint32_t hi = (uint32_t)(k16 >> 2) << 14;
    int kk = k16 & 3;
#pragma unroll
    for (int m = 0; m < 4; ++m) {
        int row = wm * 64 + m * 16 + lrA;
        uint32_t off = hi + ((uint32_t)row << 7) + ((uint32_t)((kk * 2 + lcA) ^ (row & 7)) << 4);
        ldsm4(f.a[m], sA + off);
    }
#pragma unroll
    for (int p = 0; p < 2; ++p) {
        int row = wn * 32 + p * 16 + lrB;
        uint32_t off = hi + ((uint32_t)row << 7) + ((uint32_t)((kk * 2 + lcB) ^ (row & 7)) << 4);
        uint32_t r4[4];
        ldsm4(r4, sB + off);
        f.b[2*p][0] = r4[0]; f.b[2*p][1] = r4[1]; f.b[2*p+1][0] = r4[2]; f.b[2*p+1][1] = r4[3];
    }
}

// stage layout: [A-lo 16K | A-hi 16K | B-lo 16K | B-hi 16K]
__device__ __forceinline__ void load_stage3(uint32_t sb, int tid, int k0,
                                            int row0, int bdrow) {
#pragma unroll
    for (int i = 0; i < 16; ++i) {
        int q = tid + (i << 8);               // 4096 chunks
        int half = q >> 11;                   // 0:A 1:B
        int q2 = q & 2047;
        int hi = q2 >> 10;                    // k-lo / k-hi sub-tile
        int q10 = q2 & 1023;
        int r = q10 >> 3, c = q10 & 7;
        uint32_t so = sb + ((uint32_t)half << 15) + ((uint32_t)hi << 14)
                    + (r << 7) + ((c ^ (r & 7)) << 4);
        const __half* base = half ? (g_Wd + (size_t)(bdrow + r) * FFD)
                                  : (g_H  + (size_t)(row0 + r) * FFD);
        cp16(so, base + k0 + (hi << 6) + (c << 3));
    }
    asm volatile("cp.async.commit_group;\n" ::: "memory");
}

__global__ void __launch_bounds__(256, 1)
gemm3_kernel(float* __restrict__ outp)
{
    int n0t = (g_cnt[0] + 127) >> 7, n1t = (g_cnt[1] + 127) >> 7;
    int tt = blockIdx.y;
    if (tt >= n0t + n1t) return;
    int expert = (tt < n0t) ? 0 : 1;
    int row0 = tt << 7;
    int col0 = blockIdx.x << 7;               // 128-wide col tiles
    int bdrow = expert * DDim + col0;

    extern __shared__ char smem[];
    uint32_t sbase = (uint32_t)__cvta_generic_to_shared(smem);
    int tid = threadIdx.x, wid = tid >> 5, lane = tid & 31;
    int wm = wid & 1, wn = wid >> 1;

    int lrA = (lane & 7) + (((lane >> 3) & 1) << 3);
    int lcA = lane >> 4;
    int lrB = (lane & 7) + ((lane >> 4) << 3);
    int lcB = (lane >> 3) & 1;

    float acc[4][4][4];
#pragma unroll
    for (int m = 0; m < 4; ++m)
#pragma unroll
        for (int n = 0; n < 4; ++n)
#pragma unroll
            for (int i = 0; i < 4; ++i) acc[m][n][i] = 0.f;

    const int kTiles = FFD >> 7;              // 64
    load_stage3(sbase, tid, 0, row0, bdrow);
    Frag3 fr[2];

    for (int kt = 0; kt < kTiles; ++kt) {
        asm volatile("cp.async.wait_group 0;\n" ::: "memory");
        __syncthreads();
        uint32_t sb = sbase + (uint32_t)(kt & 1) * STAGE3;
        uint32_t sA = sb, sB = sb + 32768;

        fetch3(fr[0], sA, sB, 0, wm, wn, lrA, lcA, lrB, lcB);
        if (kt + 1 < kTiles)
            load_stage3(sbase + (uint32_t)((kt + 1) & 1) * STAGE3, tid,
                        (kt + 1) << 7, row0, bdrow);
#pragma unroll
        for (int k16 = 0; k16 < 8; ++k16) {
            int cur = k16 & 1;
            if (k16 < 7)
                fetch3(fr[cur ^ 1], sA, sB, k16 + 1, wm, wn, lrA, lcA, lrB, lcB);
#pragma unroll
            for (int m = 0; m < 4; ++m)
#pragma unroll
                for (int n = 0; n < 4; ++n)
                    mma_f16(acc[m][n], fr[cur].a[m], fr[cur].b[n]);
        }
    }

    // epilogue: scale by routing weight, scatter to token rows
#pragma unroll
    for (int m = 0; m < 4; ++m) {
        int r0g = row0 + wm * 64 + m * 16 + (lane >> 2);
        int tok0 = g_tok[r0g];
        int tok1 = g_tok[r0g + 8];
        float w0 = (tok0 >= 0) ? g_topw[tok0] : 0.f;
        float w1 = (tok1 >= 0) ? g_topw[tok1] : 0.f;
#pragma unroll
        for (int n = 0; n < 4; ++n) {
            int gcol = col0 + wn * 32 + n * 8 + (lane & 3) * 2;
            if (tok0 >= 0) {
                float2 v; v.x = w0 * acc[m][n][0]; v.y = w0 * acc[m][n][1];
                *(float2*)(outp + (size_t)tok0 * DDim + gcol) = v;
            }
            if (tok1 >= 0) {
                float2 v; v.x = w1 * acc[m][n][2]; v.y = w1 * acc[m][n][3];
                *(float2*)(outp + (size_t)tok1 * DDim + gcol) = v;
            }
        }
    }
}

// ---------------- launch ----------------
extern "C" void kernel_launch(void* const* d_in, const int* in_sizes, int n_in,
                              void* d_out, int out_size)
{
    const float* x  = (const float*)d_in[0];
    const float* gw = (const float*)d_in[1];
    const float* wg = (const float*)d_in[2];
    const float* wu = (const float*)d_in[3];
    const float* wd = (const float*)d_in[4];
    float* out = (float*)d_out;

    static cudaStream_t s2 = nullptr;
    static cudaEvent_t evFork = nullptr, evGU = nullptr, evD = nullptr;
    if (s2 == nullptr) {
        cudaStreamCreateWithFlags(&s2, cudaStreamNonBlocking);
        cudaEventCreateWithFlags(&evFork, cudaEventDisableTiming);
        cudaEventCreateWithFlags(&evGU, cudaEventDisableTiming);
        cudaEventCreateWithFlags(&evD, cudaEventDisableTiming);
    }

    cudaFuncSetAttribute(gemm12_kernel, cudaFuncAttributeMaxDynamicSharedMemorySize, SMEM12);
    cudaFuncSetAttribute(gemm3_kernel,  cudaFuncAttributeMaxDynamicSharedMemorySize, SMEM3);

    // fork wconv at the very start (shares no state with the router chain)
    cudaEventRecord(evFork, 0);
    cudaStreamWaitEvent(s2, evFork, 0);

    int wblocks8 = (int)(((size_t)NE * FFD * DDim / 8 + 511) / 512);
    wconv_gu_kernel<<<dim3(wblocks8, 2), 512, 0, s2>>>(wg, wu);
    cudaEventRecord(evGU, s2);
    wconv_d_kernel<<<wblocks8, 512, 0, s2>>>(wd);
    cudaEventRecord(evD, s2);

    // main: router chain (parallel with wconv)
    init_kernel<<<(PADT + 255) / 256, 256>>>();
    router_kernel<<<(TT * 32) / 256, 256>>>(x, gw);
    assign_gather_kernel<<<(TT * 32) / 256, 256>>>(x);

    cudaStreamWaitEvent(0, evGU, 0);
    gemm12_kernel<<<dim3(NT, FFD / 128), 256, SMEM12>>>();

    cudaStreamWaitEvent(0, evD, 0);
    gemm3_kernel<<<dim3(DDim / 128, NT), 256, SMEM3>>>(out);
}

// round 14
// speedup vs baseline: 1.2412x; 1.0007x over previous
#include <cuda_runtime.h>
#include <cuda_fp16.h>
#include <stdint.h>

#define TT   8192
#define DDim 2048
#define FFD  8192
#define NE   2
#define PADT 8448      // 66*128
#define NT   66
#define STAGE12 98304  // [A-lo|A-hi|Bg-lo|Bg-hi|Bu-lo|Bu-hi] 6x16KB
#define STAGE3  65536  // [A-lo|A-hi|B-lo|B-hi] 4x16KB
#define SMEM12 (2*STAGE12)
#define SMEM3  (2*STAGE3)

// ---------------- scratch ----------------
__device__ __align__(256) __half g_Xh[(size_t)PADT*DDim];
__device__ __align__(256) __half g_Wg[(size_t)NE*FFD*DDim];
__device__ __align__(256) __half g_Wu[(size_t)NE*FFD*DDim];
__device__ __align__(256) __half g_Wd[(size_t)NE*DDim*FFD];
__device__ __align__(256) __half g_H[(size_t)PADT*FFD];
__device__ int   g_sel[TT];
__device__ float g_topw[TT];
__device__ int   g_tok[PADT];
__device__ int   g_cnt[2];
__device__ int   g_pos[2];

// ---------------- helpers ----------------
__device__ __forceinline__ void cp16(uint32_t saddr, const void* gaddr) {
    asm volatile("cp.async.cg.shared.global [%0], [%1], 16;\n"
                 :: "r"(saddr), "l"(gaddr) : "memory");
}
__device__ __forceinline__ void ldsm4(uint32_t* r, uint32_t addr) {
    asm volatile("ldmatrix.sync.aligned.m8n8.x4.shared.b16 {%0,%1,%2,%3}, [%4];\n"
                 : "=r"(r[0]), "=r"(r[1]), "=r"(r[2]), "=r"(r[3])
                 : "r"(addr) : "memory");
}
__device__ __forceinline__ void mma_f16(float* c, const uint32_t* a, const uint32_t* b) {
    asm volatile("mma.sync.aligned.m16n8k16.row.col.f32.f16.f16.f32 "
                 "{%0,%1,%2,%3}, {%4,%5,%6,%7}, {%8,%9}, {%0,%1,%2,%3};\n"
                 : "+f"(c[0]), "+f"(c[1]), "+f"(c[2]), "+f"(c[3])
                 : "r"(a[0]), "r"(a[1]), "r"(a[2]), "r"(a[3]),
                   "r"(b[0]), "r"(b[1]));
}
__device__ __forceinline__ uint32_t pack_h2(float a, float b) {
    __half2 h = __halves2half2(__float2half(a), __float2half(b));
    return *(uint32_t*)&h;
}

// ---------------- small kernels ----------------
__global__ void init_kernel() {
    int i = blockIdx.x * blockDim.x + threadIdx.x;
    if (i < PADT) g_tok[i] = -1;
    if (i == 0) { g_cnt[0] = 0; g_cnt[1] = 0; g_pos[0] = 0; g_pos[1] = 0; }
}

__global__ void router_kernel(const float* __restrict__ x, const float* __restrict__ gw) {
    int gt = blockIdx.x * blockDim.x + threadIdx.x;
    int t = gt >> 5, lane = gt & 31;
    if (t >= TT) return;
    const float* xr = x + (size_t)t * DDim;
    float a0 = 0.f, a1 = 0.f;
    for (int d = lane; d < DDim; d += 32) {
        float xv = xr[d];
        a0 += xv * gw[d];
        a1 += xv * gw[DDim + d];
    }
#pragma unroll
    for (int o = 16; o; o >>= 1) {
        a0 += __shfl_xor_sync(0xffffffffu, a0, o);
        a1 += __shfl_xor_sync(0xffffffffu, a1, o);
    }
    if (lane == 0) {
        int sel = (a0 >= a1) ? 0 : 1;
        float m = fmaxf(a0, a1);
        float e0 = expf(a0 - m), e1 = expf(a1 - m);
        float p = ((sel == 0) ? e0 : e1) / (e0 + e1);
        g_sel[t] = sel;
        g_topw[t] = p;
        atomicAdd(&g_cnt[sel], 1);
    }
}

// fused assign + gather: one warp per token claims a slot, copies/converts the row.
__global__ void assign_gather_kernel(const float* __restrict__ x) {
    int gt = blockIdx.x * blockDim.x + threadIdx.x;
    int t = gt >> 5, lane = gt & 31;
    if (t >= TT) return;
    int slot = 0;
    if (lane == 0) {
        int sel = g_sel[t];
        int base = sel ? (((g_cnt[0] + 127) >> 7) << 7) : 0;
        int p = atomicAdd(&g_pos[sel], 1);
        slot = base + p;
        g_tok[slot] = t;
    }
    slot = __shfl_sync(0xffffffffu, slot, 0);
    const float4* xr = (const float4*)(x + (size_t)t * DDim);
    __half* dst = g_Xh + (size_t)slot * DDim;
#pragma unroll 4
    for (int c = lane; c < DDim / 4; c += 32) {
        float4 v = __ldcs(xr + c);
        uint2 o;
        o.x = pack_h2(v.x, v.y);
        o.y = pack_h2(v.z, v.w);
        *(uint2*)(dst + c * 4) = o;   // normal store: re-read soon by gemm12
    }
}

// streaming fp32->fp16 weight conversion: 16 floats/thread, non-temporal.
__global__ void __launch_bounds__(512)
wconv_gu_kernel(const float* __restrict__ wg, const float* __restrict__ wu) {
    const size_t n16 = (size_t)NE * FFD * DDim / 16;
    size_t idx = (size_t)blockIdx.x * blockDim.x + threadIdx.x;
    if (idx >= n16) return;
    const float* src = (blockIdx.y == 0) ? wg : wu;
    __half* dst = (blockIdx.y == 0) ? g_Wg : g_Wu;
    const float4* s4 = (const float4*)src + idx * 4;
    float4 v0 = __ldcs(s4);
    float4 v1 = __ldcs(s4 + 1);
    float4 v2 = __ldcs(s4 + 2);
    float4 v3 = __ldcs(s4 + 3);
    uint4 o0, o1;
    o0.x = pack_h2(v0.x, v0.y); o0.y = pack_h2(v0.z, v0.w);
    o0.z = pack_h2(v1.x, v1.y); o0.w = pack_h2(v1.z, v1.w);
    o1.x = pack_h2(v2.x, v2.y); o1.y = pack_h2(v2.z, v2.w);
    o1.z = pack_h2(v3.x, v3.y); o1.w = pack_h2(v3.z, v3.w);
    __stcs((uint4*)(dst + idx * 16), o0);
    __stcs((uint4*)(dst + idx * 16) + 1, o1);
}

__global__ void __launch_bounds__(512)
wconv_d_kernel(const float* __restrict__ wd) {
    const size_t n16 = (size_t)NE * FFD * DDim / 16;
    size_t idx = (size_t)blockIdx.x * blockDim.x + threadIdx.x;
    if (idx >= n16) return;
    const float4* s4 = (const float4*)wd + idx * 4;
    float4 v0 = __ldcs(s4);
    float4 v1 = __ldcs(s4 + 1);
    float4 v2 = __ldcs(s4 + 2);
    float4 v3 = __ldcs(s4 + 3);
    uint4 o0, o1;
    o0.x = pack_h2(v0.x, v0.y); o0.y = pack_h2(v0.z, v0.w);
    o0.z = pack_h2(v1.x, v1.y); o0.w = pack_h2(v1.z, v1.w);
    o1.x = pack_h2(v2.x, v2.y); o1.y = pack_h2(v2.z, v2.w);
    o1.z = pack_h2(v3.x, v3.y); o1.w = pack_h2(v3.z, v3.w);
    __stcs((uint4*)(g_Wd + idx * 16), o0);
    __stcs((uint4*)(g_Wd + idx * 16) + 1, o1);
}

// ============ fused gate+up GEMM: tile M128 x N128 x K128-slab ============
struct Frag12 { uint32_t a[4][4]; uint32_t g[4][2]; uint32_t u[4][2]; };

__device__ __forceinline__ void fetch12(Frag12& f, uint32_t sA, uint32_t sBg, uint32_t sBu,
                                        int k16, int wm, int wn,
                                        int lrA, int lcA, int lrB, int lcB) {
    uint32_t hi = (uint32_t)(k16 >> 2) << 14;
    int kk = k16 & 3;
#pragma unroll
    for (int m = 0; m < 4; ++m) {
        int row = wm * 64 + m * 16 + lrA;
        uint32_t off = hi + ((uint32_t)row << 7) + ((uint32_t)((kk * 2 + lcA) ^ (row & 7)) << 4);
        ldsm4(f.a[m], sA + off);
    }
#pragma unroll
    for (int p = 0; p < 2; ++p) {
        int row = wn * 32 + p * 16 + lrB;
        uint32_t off = hi + ((uint32_t)row << 7) + ((uint32_t)((kk * 2 + lcB) ^ (row & 7)) << 4);
        uint32_t r4[4];
        ldsm4(r4, sBg + off);
        f.g[2*p][0] = r4[0]; f.g[2*p][1] = r4[1]; f.g[2*p+1][0] = r4[2]; f.g[2*p+1][1] = r4[3];
        ldsm4(r4, sBu + off);
        f.u[2*p][0] = r4[0]; f.u[2*p][1] = r4[1]; f.u[2*p+1][0] = r4[2]; f.u[2*p+1][1] = r4[3];
    }
}

__device__ __forceinline__ void load_stage12(uint32_t sb, int tid, int k0,
                                             int row0, int bgrow) {
#pragma unroll
    for (int i = 0; i < 24; ++i) {
        int q = tid + (i << 8);
        int mat = q >> 10;
        int q10 = q & 1023;
        int r = q10 >> 3;
        int c = q10 & 7;
        uint32_t so = sb + ((uint32_t)mat << 14) + (r << 7) + ((c ^ (r & 7)) << 4);
        int kk = k0 + ((mat & 1) << 6) + (c << 3);
        int sel = mat >> 1;
        const __half* base = (sel == 0) ? (g_Xh + (size_t)(row0 + r) * DDim)
                           : (sel == 1) ? (g_Wg + (size_t)(bgrow + r) * DDim)
                                        : (g_Wu + (size_t)(bgrow + r) * DDim);
        cp16(so, base + kk);
    }
    asm volatile("cp.async.commit_group;\n" ::: "memory");
}

__global__ void __launch_bounds__(256, 1)
gemm12_kernel()
{
    int n0t = (g_cnt[0] + 127) >> 7, n1t = (g_cnt[1] + 127) >> 7;
    int tt = blockIdx.x;
    if (tt >= n0t + n1t) return;
    int expert = (tt < n0t) ? 0 : 1;
    int row0 = tt << 7;
    int col0 = blockIdx.y << 7;
    int bgrow = expert * FFD + col0;

    extern __shared__ char smem[];
    uint32_t sbase = (uint32_t)__cvta_generic_to_shared(smem);
    int tid = threadIdx.x, wid = tid >> 5, lane = tid & 31;
    int wm = wid & 1, wn = wid >> 1;

    int lrA = (lane & 7) + (((lane >> 3) & 1) << 3);
    int lcA = lane >> 4;
    int lrB = (lane & 7) + ((lane >> 4) << 3);
    int lcB = (lane >> 3) & 1;

    float ag[4][4][4], au[4][4][4];
#pragma unroll
    for (int m = 0; m < 4; ++m)
#pragma unroll
        for (int n = 0; n < 4; ++n)
#pragma unroll
            for (int i = 0; i < 4; ++i) { ag[m][n][i] = 0.f; au[m][n][i] = 0.f; }

    const int kTiles = DDim >> 7;             // 16
    load_stage12(sbase, tid, 0, row0, bgrow);
    Frag12 fr[2];

    for (int kt = 0; kt < kTiles; ++kt) {
        asm volatile("cp.async.wait_group 0;\n" ::: "memory");
        __syncthreads();
        uint32_t sb = sbase + (uint32_t)(kt & 1) * STAGE12;
        uint32_t sA = sb, sBg = sb + 32768, sBu = sb + 65536;

        fetch12(fr[0], sA, sBg, sBu, 0, wm, wn, lrA, lcA, lrB, lcB);
        if (kt + 1 < kTiles)
            load_stage12(sbase + (uint32_t)((kt + 1) & 1) * STAGE12, tid,
                         (kt + 1) << 7, row0, bgrow);
#pragma unroll
        for (int k16 = 0; k16 < 8; ++k16) {
            int cur = k16 & 1;
            if (k16 < 7)
                fetch12(fr[cur ^ 1], sA, sBg, sBu, k16 + 1, wm, wn, lrA, lcA, lrB, lcB);
#pragma unroll
            for (int m = 0; m < 4; ++m)
#pragma unroll
                for (int n = 0; n < 4; ++n) {
                    mma_f16(ag[m][n], fr[cur].a[m], fr[cur].g[n]);
                    mma_f16(au[m][n], fr[cur].a[m], fr[cur].u[n]);
                }
        }
    }

    // epilogue: h = silu(g) * u -> fp16 H
#pragma unroll
    for (int m = 0; m < 4; ++m) {
        int grow = row0 + wm * 64 + m * 16 + (lane >> 2);
#pragma unroll
        for (int n = 0; n < 4; ++n) {
            int gcol = col0 + wn * 32 + n * 8 + (lane & 3) * 2;
            float h0 = ag[m][n][0] * au[m][n][0] / (1.f + expf(-ag[m][n][0]));
            float h1 = ag[m][n][1] * au[m][n][1] / (1.f + expf(-ag[m][n][1]));
            float h2 = ag[m][n][2] * au[m][n][2] / (1.f + expf(-ag[m][n][2]));
            float h3 = ag[m][n][3] * au[m][n][3] / (1.f + expf(-ag[m][n][3]));
            *(uint32_t*)(g_H + (size_t)grow * FFD + gcol)       = pack_h2(h0, h1);
            *(uint32_t*)(g_H + (size_t)(grow + 8) * FFD + gcol) = pack_h2(h2, h3);
        }
    }
}

// ============ down GEMM: tile M128 x N128 x K128-slab ============
struct Frag3 { uint32_t a[4][4]; uint32_t b[4][2]; };

__device__ __forceinline__ void fetch3(Frag3& f, uint32_t sA, uint32_t sB,
                                       int k16, int wm, int wn,
                                       int lrA, int lcA, int lrB, int lcB) {
    uint32_t hi = (uint32_t)(k16 >> 2) << 14;
    int kk = k16 & 3;
#pragma unroll
    for (int m = 0; m < 4; ++m) {
        int row = wm * 64 + m * 16 + lrA;
        uint32_t off = hi + ((uint32_t)row << 7) + ((uint32_t)((kk * 2 + lcA) ^ (row & 7)) << 4);
        ldsm4(f.a[m], sA + off);
    }
#pragma unroll
    for (int p = 0; p < 2; ++p) {
        int row = wn * 32 + p * 16 + lrB;
        uint32_t off = hi + ((uint32_t)row << 7) + ((uint32_t)((kk * 2 + lcB) ^ (row & 7)) << 4);
        uint32_t r4[4];
        ldsm4(r4, sB + off);
        f.b[2*p][0] = r4[0]; f.b[2*p][1] = r4[1]; f.b[2*p+1][0] = r4[2]; f.b[2*p+1][1] = r4[3];
    }
}

// stage layout: [A-lo 16K | A-hi 16K | B-lo 16K | B-hi 16K]
__device__ __forceinline__ void load_stage3(uint32_t sb, int tid, int k0,
                                            int row0, int bdrow) {
#pragma unroll
    for (int i = 0; i < 16; ++i) {
        int q = tid + (i << 8);               // 4096 chunks
        int half = q >> 11;                   // 0:A 1:B
        int q2 = q & 2047;
        int hi = q2 >> 10;                    // k-lo / k-hi sub-tile
        int q10 = q2 & 1023;
        int r = q10 >> 3, c = q10 & 7;
        uint32_t so = sb + ((uint32_t)half << 15) + ((uint32_t)hi << 14)
                    + (r << 7) + ((c ^ (r & 7)) << 4);
        const __half* base = half ? (g_Wd + (size_t)(bdrow + r) * FFD)
                                  : (g_H  + (size_t)(row0 + r) * FFD);
        cp16(so, base + k0 + (hi << 6) + (c << 3));
    }
    asm volatile("cp.async.commit_group;\n" ::: "memory");
}

__global__ void __launch_bounds__(256, 1)
gemm3_kernel(float* __restrict__ outp)
{
    int n0t = (g_cnt[0] + 127) >> 7, n1t = (g_cnt[1] + 127) >> 7;
    int tt = blockIdx.y;
    if (tt >= n0t + n1t) return;
    int expert = (tt < n0t) ? 0 : 1;
    int row0 = tt << 7;
    int col0 = blockIdx.x << 7;
    int bdrow = expert * DDim + col0;

    extern __shared__ char smem[];
    uint32_t sbase = (uint32_t)__cvta_generic_to_shared(smem);
    int tid = threadIdx.x, wid = tid >> 5, lane = tid & 31;
    int wm = wid & 1, wn = wid >> 1;

    int lrA = (lane & 7) + (((lane >> 3) & 1) << 3);
    int lcA = lane >> 4;
    int lrB = (lane & 7) + ((lane >> 4) << 3);
    int lcB = (lane >> 3) & 1;

    float acc[4][4][4];
#pragma unroll
    for (int m = 0; m < 4; ++m)
#pragma unroll
        for (int n = 0; n < 4; ++n)
#pragma unroll
            for (int i = 0; i < 4; ++i) acc[m][n][i] = 0.f;

    const int kTiles = FFD >> 7;              // 64
    load_stage3(sbase, tid, 0, row0, bdrow);
    Frag3 fr[2];

    for (int kt = 0; kt < kTiles; ++kt) {
        asm volatile("cp.async.wait_group 0;\n" ::: "memory");
        __syncthreads();
        uint32_t sb = sbase + (uint32_t)(kt & 1) * STAGE3;
        uint32_t sA = sb, sB = sb + 32768;

        fetch3(fr[0], sA, sB, 0, wm, wn, lrA, lcA, lrB, lcB);
        if (kt + 1 < kTiles)
            load_stage3(sbase + (uint32_t)((kt + 1) & 1) * STAGE3, tid,
                        (kt + 1) << 7, row0, bdrow);
#pragma unroll
        for (int k16 = 0; k16 < 8; ++k16) {
            int cur = k16 & 1;
            if (k16 < 7)
                fetch3(fr[cur ^ 1], sA, sB, k16 + 1, wm, wn, lrA, lcA, lrB, lcB);
#pragma unroll
            for (int m = 0; m < 4; ++m)
#pragma unroll
                for (int n = 0; n < 4; ++n)
                    mma_f16(acc[m][n], fr[cur].a[m], fr[cur].b[n]);
        }
    }

    // epilogue: scale by routing weight, streaming scatter to token rows
#pragma unroll
    for (int m = 0; m < 4; ++m) {
        int r0g = row0 + wm * 64 + m * 16 + (lane >> 2);
        int tok0 = g_tok[r0g];
        int tok1 = g_tok[r0g + 8];
        float w0 = (tok0 >= 0) ? g_topw[tok0] : 0.f;
        float w1 = (tok1 >= 0) ? g_topw[tok1] : 0.f;
#pragma unroll
        for (int n = 0; n < 4; ++n) {
            int gcol = col0 + wn * 32 + n * 8 + (lane & 3) * 2;
            if (tok0 >= 0) {
                float2 v; v.x = w0 * acc[m][n][0]; v.y = w0 * acc[m][n][1];
                __stcs((float2*)(outp + (size_t)tok0 * DDim + gcol), v);
            }
            if (tok1 >= 0) {
                float2 v; v.x = w1 * acc[m][n][2]; v.y = w1 * acc[m][n][3];
                __stcs((float2*)(outp + (size_t)tok1 * DDim + gcol), v);
            }
        }
    }
}

// ---------------- launch ----------------
extern "C" void kernel_launch(void* const* d_in, const int* in_sizes, int n_in,
                              void* d_out, int out_size)
{
    const float* x  = (const float*)d_in[0];
    const float* gw = (const float*)d_in[1];
    const float* wg = (const float*)d_in[2];
    const float* wu = (const float*)d_in[3];
    const float* wd = (const float*)d_in[4];
    float* out = (float*)d_out;

    static cudaStream_t s2 = nullptr;
    static cudaEvent_t evFork = nullptr, evGU = nullptr, evD = nullptr;
    if (s2 == nullptr) {
        cudaStreamCreateWithFlags(&s2, cudaStreamNonBlocking);
        cudaEventCreateWithFlags(&evFork, cudaEventDisableTiming);
        cudaEventCreateWithFlags(&evGU, cudaEventDisableTiming);
        cudaEventCreateWithFlags(&evD, cudaEventDisableTiming);
    }

    cudaFuncSetAttribute(gemm12_kernel, cudaFuncAttributeMaxDynamicSharedMemorySize, SMEM12);
    cudaFuncSetAttribute(gemm3_kernel,  cudaFuncAttributeMaxDynamicSharedMemorySize, SMEM3);

    // fork wconv at the very start (shares no state with the router chain)
    cudaEventRecord(evFork, 0);
    cudaStreamWaitEvent(s2, evFork, 0);

    int wblocks16 = (int)(((size_t)NE * FFD * DDim / 16 + 511) / 512);
    wconv_gu_kernel<<<dim3(wblocks16, 2), 512, 0, s2>>>(wg, wu);
    cudaEventRecord(evGU, s2);
    wconv_d_kernel<<<wblocks16, 512, 0, s2>>>(wd);
    cudaEventRecord(evD, s2);

    // main: router chain (parallel with wconv)
    init_kernel<<<(PADT + 255) / 256, 256>>>();
    router_kernel<<<(TT * 32) / 256, 256>>>(x, gw);
    assign_gather_kernel<<<(TT * 32) / 256, 256>>>(x);

    cudaStreamWaitEvent(0, evGU, 0);
    gemm12_kernel<<<dim3(NT, FFD / 128), 256, SMEM12>>>();

    cudaStreamWaitEvent(0, evD, 0);
    gemm3_kernel<<<dim3(DDim / 128, NT), 256, SMEM3>>>(out);
}